// round 5
// baseline (speedup 1.0000x reference)
#include <cuda_runtime.h>
#include <cstddef>

#define NN    50000
#define EE    800000
#define IN_D  512
#define HID_D 256
#define LAT_D 128

// ---- static device scratch (no allocations allowed; referenced directly in device code) ----
__device__ __align__(16) float g_deg[NN];
__device__ __align__(16) float g_dis[NN];
__device__ __align__(16) float g_norm[EE];
__device__ __align__(16) float g_h1[(size_t)NN * HID_D];      // x@W1, later reused as agg2
__device__ __align__(16) float g_agg[(size_t)NN * HID_D];     // agg1 (pre-relu)
__device__ __align__(16) float g_hidden[(size_t)NN * HID_D];  // relu(agg1 + b1)

// ---------------- degree / norm ----------------
__global__ void k_init_deg() {
    int i = blockIdx.x * blockDim.x + threadIdx.x;
    if (i < NN) g_deg[i] = 1.0f;  // self-loop weight 1
}

__global__ void k_deg_accum(const int* __restrict__ ei,
                            const float* __restrict__ ea) {
    int e = blockIdx.x * blockDim.x + threadIdx.x;
    if (e < EE) atomicAdd(&g_deg[ei[EE + e]], ea[e]);
}

__global__ void k_dis() {
    int i = blockIdx.x * blockDim.x + threadIdx.x;
    if (i < NN) {
        float d = g_deg[i];
        g_dis[i] = (d > 0.0f) ? rsqrtf(d) : 0.0f;
    }
}

__global__ void k_norm(const int* __restrict__ ei,
                       const float* __restrict__ ea) {
    int e = blockIdx.x * blockDim.x + threadIdx.x;
    if (e < EE) {
        int s = ei[e];
        int d = ei[EE + e];
        g_norm[e] = g_dis[s] * ea[e] * g_dis[d];
    }
}

// ---------------- self-loop init:  dst = dis[i]^2 * src ----------------
// PHASE 0: src = g_h1,     dst = g_agg
// PHASE 1: src = g_hidden, dst = g_h1
template<int PHASE>
__global__ void k_selfloop() {
    int idx = blockIdx.x * blockDim.x + threadIdx.x;
    if (idx < NN * HID_D) {
        const float* src = (PHASE == 0) ? g_h1 : g_hidden;
        float*       dst = (PHASE == 0) ? g_agg : g_h1;
        int i = idx >> 8;  // / 256
        float d = g_dis[i];
        dst[idx] = d * d * src[idx];
    }
}

// ---------------- edge scatter: agg[dst] += feat[src] * norm ----------------
// one thread per (edge, 4-channel group); 256 channels -> 64 groups
// PHASE 0: feat = g_h1,     agg = g_agg
// PHASE 1: feat = g_hidden, agg = g_h1
template<int PHASE>
__global__ void k_scatter(const int* __restrict__ ei) {
    long long idx = (long long)blockIdx.x * blockDim.x + threadIdx.x;
    if (idx >= (long long)EE * 64) return;
    const float* feat = (PHASE == 0) ? g_h1 : g_hidden;
    float*       agg  = (PHASE == 0) ? g_agg : g_h1;
    int e = (int)(idx >> 6);
    int c = ((int)idx & 63) << 2;
    int s = __ldg(&ei[e]);
    int d = __ldg(&ei[EE + e]);
    float n = g_norm[e];
    float4 v = *reinterpret_cast<const float4*>(feat + (size_t)s * HID_D + c);
    float* o = agg + (size_t)d * HID_D + c;
    atomicAdd(o + 0, v.x * n);
    atomicAdd(o + 1, v.y * n);
    atomicAdd(o + 2, v.z * n);
    atomicAdd(o + 3, v.w * n);
}

// ---------------- hidden = relu(agg1 + b1) ----------------
__global__ void k_relu_bias(const float* __restrict__ b1) {
    int idx = blockIdx.x * blockDim.x + threadIdx.x;
    if (idx < NN * HID_D) {
        int c = idx & 255;
        g_hidden[idx] = fmaxf(g_agg[idx] + b1[c], 0.0f);
    }
}

// ---------------- fp32 SGEMM: C[M,Ncol] = A[M,K] @ B[K,Ncol] (+bias) ----------------
// 64x64 block tile, BK=16, 256 threads, 4x4 per-thread microtile
// AMODE: 0 -> A = param Ap (harness input);  1 -> A = g_h1
// CMODE: 0 -> C = param Cp (d_out);          1 -> C = g_h1
template<int AMODE, int CMODE>
__global__ __launch_bounds__(256) void k_sgemm(
    const float* __restrict__ Ap, const float* __restrict__ B,
    const float* __restrict__ bias, float* __restrict__ Cp,
    int M, int K, int Ncol)
{
    const float* A = (AMODE == 0) ? Ap : (const float*)g_h1;
    float*       C = (CMODE == 0) ? Cp : g_h1;

    __shared__ float As[16][64];   // [k][m]
    __shared__ float Bs[16][64];   // [k][n]

    int tid = threadIdx.x;
    int tx = tid & 15;        // n-direction
    int ty = tid >> 4;        // m-direction
    int mBase = blockIdx.y * 64;
    int nBase = blockIdx.x * 64;

    float acc[4][4] = {};

    for (int k0 = 0; k0 < K; k0 += 16) {
        // Load A tile 64x16 as float4 per thread (row = tid/4, 4 cols)
        {
            int r = tid >> 2;
            int c = (tid & 3) << 2;
            int row = mBase + r;
            float4 v = make_float4(0.f, 0.f, 0.f, 0.f);
            if (row < M)
                v = *reinterpret_cast<const float4*>(A + (size_t)row * K + k0 + c);
            As[c + 0][r] = v.x;
            As[c + 1][r] = v.y;
            As[c + 2][r] = v.z;
            As[c + 3][r] = v.w;
        }
        // Load B tile 16x64 as float4 per thread (row = tid/16, 4 cols)
        {
            int r = tid >> 4;
            int c = (tid & 15) << 2;
            float4 v = *reinterpret_cast<const float4*>(B + (size_t)(k0 + r) * Ncol + nBase + c);
            *reinterpret_cast<float4*>(&Bs[r][c]) = v;
        }
        __syncthreads();

        #pragma unroll
        for (int kk = 0; kk < 16; kk++) {
            float4 a4 = *reinterpret_cast<const float4*>(&As[kk][ty << 2]);
            float4 b4 = *reinterpret_cast<const float4*>(&Bs[kk][tx << 2]);
            float av[4] = {a4.x, a4.y, a4.z, a4.w};
            float bv[4] = {b4.x, b4.y, b4.z, b4.w};
            #pragma unroll
            for (int i = 0; i < 4; i++)
                #pragma unroll
                for (int j = 0; j < 4; j++)
                    acc[i][j] += av[i] * bv[j];
        }
        __syncthreads();
    }

    int col = nBase + (tx << 2);
    float4 bb = make_float4(0.f, 0.f, 0.f, 0.f);
    if (bias) bb = *reinterpret_cast<const float4*>(bias + col);

    #pragma unroll
    for (int i = 0; i < 4; i++) {
        int row = mBase + (ty << 2) + i;
        if (row < M) {
            float4 o;
            o.x = acc[i][0] + bb.x;
            o.y = acc[i][1] + bb.y;
            o.z = acc[i][2] + bb.z;
            o.w = acc[i][3] + bb.w;
            *reinterpret_cast<float4*>(C + (size_t)row * Ncol + col) = o;
        }
    }
}

// ---------------- launch ----------------
extern "C" void kernel_launch(void* const* d_in, const int* in_sizes, int n_in,
                              void* d_out, int out_size) {
    const float* x   = (const float*)d_in[0];
    const int*   ei  = (const int*)d_in[1];     // [2, E] int32 (harness has no int64)
    const float* ea  = (const float*)d_in[2];
    const float* W1  = (const float*)d_in[3];
    const float* b1  = (const float*)d_in[4];
    const float* Wmu = (const float*)d_in[5];
    const float* bmu = (const float*)d_in[6];
    const float* Wlv = (const float*)d_in[7];
    const float* blv = (const float*)d_in[8];
    float* out = (float*)d_out;

    const int TB = 256;
    // ---- GCN normalization ----
    k_init_deg <<<(NN + TB - 1) / TB, TB>>>();
    k_deg_accum<<<(EE + TB - 1) / TB, TB>>>(ei, ea);
    k_dis      <<<(NN + TB - 1) / TB, TB>>>();
    k_norm     <<<(EE + TB - 1) / TB, TB>>>(ei, ea);

    // ---- conv1: g_h1 = x @ W1 ; g_agg = Agg(g_h1) ; g_hidden = relu(g_agg + b1) ----
    dim3 g1(HID_D / 64, (NN + 63) / 64);
    k_sgemm<0, 1><<<g1, 256>>>(x, W1, nullptr, nullptr, NN, IN_D, HID_D);

    int nElem = NN * HID_D;
    long long nScat = (long long)EE * 64;
    k_selfloop<0><<<(nElem + TB - 1) / TB, TB>>>();
    k_scatter<0><<<(int)((nScat + TB - 1) / TB), TB>>>(ei);
    k_relu_bias<<<(nElem + TB - 1) / TB, TB>>>(b1);

    // ---- agg2 = Agg(hidden)  (into g_h1) ----
    k_selfloop<1><<<(nElem + TB - 1) / TB, TB>>>();
    k_scatter<1><<<(int)((nScat + TB - 1) / TB), TB>>>(ei);

    // ---- mu = agg2 @ W_mu + b_mu ; logvar = agg2 @ W_lv + b_lv ----
    dim3 g2(LAT_D / 64, (NN + 63) / 64);
    k_sgemm<1, 0><<<g2, 256>>>(nullptr, Wmu, bmu, out, NN, HID_D, LAT_D);
    k_sgemm<1, 0><<<g2, 256>>>(nullptr, Wlv, blv, out + (size_t)NN * LAT_D, NN, HID_D, LAT_D);
}

// round 6
// speedup vs baseline: 1.5618x; 1.5618x over previous
#include <cuda_runtime.h>
#include <cstddef>

#define NN    50000
#define EE    800000
#define IN_D  512
#define HID_D 256
#define LAT_D 128

// ---- static device scratch ----
__device__ __align__(16) float g_deg[NN];
__device__ __align__(16) float g_dis[NN];
__device__ __align__(16) float g_norm[EE];
__device__ __align__(16) float g_h1[(size_t)NN * HID_D];      // x@W1, later reused as agg2
__device__ __align__(16) float g_agg[(size_t)NN * HID_D];     // agg1 (pre-relu)
__device__ __align__(16) float g_hidden[(size_t)NN * HID_D];  // relu(agg1 + b1)

// ---------------- degree / norm ----------------
__global__ void k_init_deg() {
    int i = blockIdx.x * blockDim.x + threadIdx.x;
    if (i < NN) g_deg[i] = 1.0f;
}

__global__ void k_deg_accum(const int* __restrict__ ei, const float* __restrict__ ea) {
    int e = blockIdx.x * blockDim.x + threadIdx.x;
    if (e < EE) atomicAdd(&g_deg[ei[EE + e]], ea[e]);
}

__global__ void k_dis() {
    int i = blockIdx.x * blockDim.x + threadIdx.x;
    if (i < NN) {
        float d = g_deg[i];
        g_dis[i] = (d > 0.0f) ? rsqrtf(d) : 0.0f;
    }
}

__global__ void k_norm(const int* __restrict__ ei, const float* __restrict__ ea) {
    int e = blockIdx.x * blockDim.x + threadIdx.x;
    if (e < EE) {
        int s = ei[e];
        int d = ei[EE + e];
        g_norm[e] = g_dis[s] * ea[e] * g_dis[d];
    }
}

// ---------------- self-loop init (phase 0): g_agg = dis^2 * g_h1 ----------------
__global__ void k_selfloop0() {
    int idx = blockIdx.x * blockDim.x + threadIdx.x;  // NN*64 float4 groups
    if (idx < NN * 64) {
        int i = idx >> 6;
        float ds = g_dis[i];
        float dsq = ds * ds;
        float4 v = *reinterpret_cast<const float4*>(g_h1 + (size_t)idx * 4);
        v.x *= dsq; v.y *= dsq; v.z *= dsq; v.w *= dsq;
        *reinterpret_cast<float4*>(g_agg + (size_t)idx * 4) = v;
    }
}

// ---------------- fused: hidden = relu(agg + b1); g_h1 = dis^2 * hidden ----------------
__global__ void k_relu_selfloop(const float* __restrict__ b1) {
    int idx = blockIdx.x * blockDim.x + threadIdx.x;  // NN*64 float4 groups
    if (idx < NN * 64) {
        int i = idx >> 6;
        int c = (idx & 63) << 2;
        float ds = g_dis[i];
        float dsq = ds * ds;
        float4 a = *reinterpret_cast<const float4*>(g_agg + (size_t)idx * 4);
        float4 bb = *reinterpret_cast<const float4*>(b1 + c);
        float4 h;
        h.x = fmaxf(a.x + bb.x, 0.0f);
        h.y = fmaxf(a.y + bb.y, 0.0f);
        h.z = fmaxf(a.z + bb.z, 0.0f);
        h.w = fmaxf(a.w + bb.w, 0.0f);
        *reinterpret_cast<float4*>(g_hidden + (size_t)idx * 4) = h;
        float4 o;
        o.x = dsq * h.x; o.y = dsq * h.y; o.z = dsq * h.z; o.w = dsq * h.w;
        *reinterpret_cast<float4*>(g_h1 + (size_t)idx * 4) = o;
    }
}

// ---------------- vectorized global reduction ----------------
__device__ __forceinline__ void red_add_v4(float* p, float a, float b, float c, float d) {
    asm volatile("red.global.add.v4.f32 [%0], {%1, %2, %3, %4};"
                 :: "l"(p), "f"(a), "f"(b), "f"(c), "f"(d) : "memory");
}

// ---------------- edge scatter: agg[dst] += feat[src] * norm ----------------
// one thread per (edge, 8-channel group): 32 groups per edge
// PHASE 0: feat = g_h1,     agg = g_agg
// PHASE 1: feat = g_hidden, agg = g_h1
template<int PHASE>
__global__ void k_scatter(const int* __restrict__ ei) {
    int idx = blockIdx.x * blockDim.x + threadIdx.x;  // EE*32 = 25.6M
    if (idx >= EE * 32) return;
    const float* feat = (PHASE == 0) ? g_h1 : g_hidden;
    float*       agg  = (PHASE == 0) ? g_agg : g_h1;
    int e = idx >> 5;
    int c = (idx & 31) << 3;
    int s = __ldg(&ei[e]);
    int d = __ldg(&ei[EE + e]);
    float n = g_norm[e];
    const float* f = feat + (size_t)s * HID_D + c;
    float4 v0 = *reinterpret_cast<const float4*>(f);
    float4 v1 = *reinterpret_cast<const float4*>(f + 4);
    float* o = agg + (size_t)d * HID_D + c;
    red_add_v4(o,     v0.x * n, v0.y * n, v0.z * n, v0.w * n);
    red_add_v4(o + 4, v1.x * n, v1.y * n, v1.z * n, v1.w * n);
}

// ---------------- GEMM: 128x128 block tile, BK=8, 256 threads, 8x8 microtile ----------------
// MODE 0: g_h1[NN,256] = X[NN,512] @ W1[512,256]                       grid(2, 391)
// MODE 1: out_mu/out_lv[NN,128] = g_h1[NN,256] @ Wmu/Wlv + bias        grid(2, 391)
template<int MODE>
__global__ __launch_bounds__(256) void k_gemm(
    const float* __restrict__ X,  const float* __restrict__ W1,
    const float* __restrict__ Wmu, const float* __restrict__ bmu,
    const float* __restrict__ Wlv, const float* __restrict__ blv,
    float* __restrict__ out)
{
    const float* A;
    const float* B;
    const float* bias;
    float* C;
    int K, ldb, ldc, nBase;
    if (MODE == 0) {
        A = X; B = W1; bias = nullptr; C = g_h1;
        K = IN_D; ldb = HID_D; ldc = HID_D; nBase = blockIdx.x * 128;
    } else {
        A = g_h1;
        B    = blockIdx.x ? Wlv : Wmu;
        bias = blockIdx.x ? blv : bmu;
        C = out + (size_t)blockIdx.x * NN * LAT_D;
        K = HID_D; ldb = LAT_D; ldc = LAT_D; nBase = 0;
    }
    const int M = NN;

    __shared__ float As[8][132];  // [k][m], padded
    __shared__ float Bs[8][128];  // [k][n]

    int tid = threadIdx.x;
    int tx = tid & 15;
    int ty = tid >> 4;
    int mBase = blockIdx.y * 128;

    float acc[8][8] = {};

    for (int k0 = 0; k0 < K; k0 += 8) {
        // A tile 128x8: each thread loads one float4
        {
            int ar = tid >> 1;
            int ac = (tid & 1) << 2;
            int grow = mBase + ar;
            float4 v = make_float4(0.f, 0.f, 0.f, 0.f);
            if (grow < M)
                v = *reinterpret_cast<const float4*>(A + (size_t)grow * K + k0 + ac);
            As[ac + 0][ar] = v.x;
            As[ac + 1][ar] = v.y;
            As[ac + 2][ar] = v.z;
            As[ac + 3][ar] = v.w;
        }
        // B tile 8x128: each thread loads one float4
        {
            int kr = tid >> 5;
            int bc = (tid & 31) << 2;
            float4 v = *reinterpret_cast<const float4*>(B + (size_t)(k0 + kr) * ldb + nBase + bc);
            *reinterpret_cast<float4*>(&Bs[kr][bc]) = v;
        }
        __syncthreads();

        #pragma unroll
        for (int kk = 0; kk < 8; kk++) {
            float4 a0 = *reinterpret_cast<const float4*>(&As[kk][ty << 2]);
            float4 a1 = *reinterpret_cast<const float4*>(&As[kk][64 + (ty << 2)]);
            float4 b0 = *reinterpret_cast<const float4*>(&Bs[kk][tx << 2]);
            float4 b1 = *reinterpret_cast<const float4*>(&Bs[kk][64 + (tx << 2)]);
            float a[8] = {a0.x, a0.y, a0.z, a0.w, a1.x, a1.y, a1.z, a1.w};
            float b[8] = {b0.x, b0.y, b0.z, b0.w, b1.x, b1.y, b1.z, b1.w};
            #pragma unroll
            for (int i = 0; i < 8; i++)
                #pragma unroll
                for (int j = 0; j < 8; j++)
                    acc[i][j] += a[i] * b[j];
        }
        __syncthreads();
    }

    // epilogue
    float4 bb0 = make_float4(0.f, 0.f, 0.f, 0.f);
    float4 bb1 = make_float4(0.f, 0.f, 0.f, 0.f);
    if (MODE == 1) {
        bb0 = *reinterpret_cast<const float4*>(bias + (tx << 2));
        bb1 = *reinterpret_cast<const float4*>(bias + 64 + (tx << 2));
    }

    #pragma unroll
    for (int hi = 0; hi < 2; hi++) {
        #pragma unroll
        for (int ii = 0; ii < 4; ii++) {
            int r = mBase + hi * 64 + (ty << 2) + ii;
            if (r < M) {
                int ai = hi * 4 + ii;
                float4 o0, o1;
                o0.x = acc[ai][0] + bb0.x; o0.y = acc[ai][1] + bb0.y;
                o0.z = acc[ai][2] + bb0.z; o0.w = acc[ai][3] + bb0.w;
                o1.x = acc[ai][4] + bb1.x; o1.y = acc[ai][5] + bb1.y;
                o1.z = acc[ai][6] + bb1.z; o1.w = acc[ai][7] + bb1.w;
                *reinterpret_cast<float4*>(C + (size_t)r * ldc + nBase + (tx << 2)) = o0;
                *reinterpret_cast<float4*>(C + (size_t)r * ldc + nBase + 64 + (tx << 2)) = o1;
            }
        }
    }
}

// ---------------- launch ----------------
extern "C" void kernel_launch(void* const* d_in, const int* in_sizes, int n_in,
                              void* d_out, int out_size) {
    const float* x   = (const float*)d_in[0];
    const int*   ei  = (const int*)d_in[1];     // [2, E] int32
    const float* ea  = (const float*)d_in[2];
    const float* W1  = (const float*)d_in[3];
    const float* b1  = (const float*)d_in[4];
    const float* Wmu = (const float*)d_in[5];
    const float* bmu = (const float*)d_in[6];
    const float* Wlv = (const float*)d_in[7];
    const float* blv = (const float*)d_in[8];
    float* out = (float*)d_out;

    const int TB = 256;
    // ---- GCN normalization ----
    k_init_deg <<<(NN + TB - 1) / TB, TB>>>();
    k_deg_accum<<<(EE + TB - 1) / TB, TB>>>(ei, ea);
    k_dis      <<<(NN + TB - 1) / TB, TB>>>();
    k_norm     <<<(EE + TB - 1) / TB, TB>>>(ei, ea);

    // ---- conv1 transform: g_h1 = x @ W1 ----
    dim3 g1(2, (NN + 127) / 128);
    k_gemm<0><<<g1, 256>>>(x, W1, nullptr, nullptr, nullptr, nullptr, nullptr);

    int nVec = NN * 64;          // float4 groups
    int nScat = EE * 32;         // 25.6M threads
    // ---- aggregate conv1 ----
    k_selfloop0<<<(nVec + TB - 1) / TB, TB>>>();
    k_scatter<0><<<(nScat + TB - 1) / TB, TB>>>(ei);
    // ---- hidden = relu(agg + b1); seed agg2 self-loop into g_h1 ----
    k_relu_selfloop<<<(nVec + TB - 1) / TB, TB>>>(b1);
    // ---- aggregate conv2 (into g_h1) ----
    k_scatter<1><<<(nScat + TB - 1) / TB, TB>>>(ei);

    // ---- mu / logvar GEMMs fused in one launch ----
    dim3 g2(2, (NN + 127) / 128);
    k_gemm<1><<<g2, 256>>>(nullptr, nullptr, Wmu, bmu, Wlv, blv, out);
}

// round 7
// speedup vs baseline: 2.5800x; 1.6519x over previous
#include <cuda_runtime.h>
#include <cstddef>
#include <cstdint>

#define NN    50000
#define EE    800000
#define IN_D  512
#define HID_D 256
#define LAT_D 128
#define SCB   196      // ceil(NN/256) scan blocks

typedef unsigned long long u64;

// ---- static device scratch ----
__device__ __align__(16) float g_deg[NN];
__device__ __align__(16) float g_dis[NN];
__device__ __align__(16) float g_norm[EE];
__device__ __align__(16) float g_h1[(size_t)NN * HID_D];      // x@W1, later agg2
__device__ __align__(16) float g_hidden[(size_t)NN * HID_D];  // relu(agg1 + b1)
// CSR
__device__ int   g_cnt[NN];
__device__ int   g_rowptr[NN + 1];
__device__ int   g_bsum[256];
__device__ int   g_srcs[EE];
__device__ __align__(8) float g_nrm2[EE];

// ---------------- f32x2 helpers ----------------
__device__ __forceinline__ u64 fma2(u64 a, u64 b, u64 c) {
    u64 d;
    asm("fma.rn.f32x2 %0, %1, %2, %3;" : "=l"(d) : "l"(a), "l"(b), "l"(c));
    return d;
}
__device__ __forceinline__ u64 bcast2(float x) {
    u64 d;
    unsigned u = __float_as_uint(x);
    asm("mov.b64 %0, {%1, %1};" : "=l"(d) : "r"(u));
    return d;
}
__device__ __forceinline__ float lo2(u64 v) { return __uint_as_float((unsigned)v); }
__device__ __forceinline__ float hi2(u64 v) { return __uint_as_float((unsigned)(v >> 32)); }

// ---------------- degree / norm ----------------
__global__ void k_init_deg() {
    int i = blockIdx.x * blockDim.x + threadIdx.x;
    if (i < NN) g_deg[i] = 1.0f;
}
__global__ void k_deg_accum(const int* __restrict__ ei, const float* __restrict__ ea) {
    int e = blockIdx.x * blockDim.x + threadIdx.x;
    if (e < EE) atomicAdd(&g_deg[ei[EE + e]], ea[e]);
}
__global__ void k_dis() {
    int i = blockIdx.x * blockDim.x + threadIdx.x;
    if (i < NN) {
        float d = g_deg[i];
        g_dis[i] = (d > 0.0f) ? rsqrtf(d) : 0.0f;
    }
}
__global__ void k_norm(const int* __restrict__ ei, const float* __restrict__ ea) {
    int e = blockIdx.x * blockDim.x + threadIdx.x;
    if (e < EE) {
        int s = ei[e];
        int d = ei[EE + e];
        g_norm[e] = g_dis[s] * ea[e] * g_dis[d];
    }
}

// ---------------- CSR build (counting sort by dst) ----------------
__global__ void k_zero_cnt() {
    int i = blockIdx.x * blockDim.x + threadIdx.x;
    if (i < NN) g_cnt[i] = 0;
}
__global__ void k_hist(const int* __restrict__ ei) {
    int e = blockIdx.x * blockDim.x + threadIdx.x;
    if (e < EE) atomicAdd(&g_cnt[ei[EE + e]], 1);
}
__global__ void k_scan1() {
    __shared__ int s[256];
    int t = threadIdx.x;
    int i = blockIdx.x * 256 + t;
    int v = (i < NN) ? g_cnt[i] : 0;
    s[t] = v;
    #pragma unroll
    for (int off = 1; off < 256; off <<= 1) {
        __syncthreads();
        int add = (t >= off) ? s[t - off] : 0;
        __syncthreads();
        s[t] += add;
    }
    __syncthreads();
    if (i < NN) g_rowptr[i] = s[t] - v;       // exclusive within block
    if (t == 255) g_bsum[blockIdx.x] = s[255];
}
__global__ void k_scan2() {
    __shared__ int s[256];
    int t = threadIdx.x;
    int v = (t < SCB) ? g_bsum[t] : 0;
    s[t] = v;
    #pragma unroll
    for (int off = 1; off < 256; off <<= 1) {
        __syncthreads();
        int add = (t >= off) ? s[t - off] : 0;
        __syncthreads();
        s[t] += add;
    }
    __syncthreads();
    if (t < SCB) g_bsum[t] = s[t] - v;        // exclusive block offsets
}
__global__ void k_scan3() {
    int i = blockIdx.x * blockDim.x + threadIdx.x;
    if (i < NN) {
        int r = g_rowptr[i] + g_bsum[i >> 8];
        g_rowptr[i] = r;
        g_cnt[i] = r;   // running cursor for fill
    }
    if (i == 0) g_rowptr[NN] = EE;
}
__global__ void k_fill(const int* __restrict__ ei) {
    int e = blockIdx.x * blockDim.x + threadIdx.x;
    if (e < EE) {
        int d = ei[EE + e];
        int pos = atomicAdd(&g_cnt[d], 1);
        g_srcs[pos] = ei[e];
        g_nrm2[pos] = g_norm[e];
    }
}

// ---------------- gather aggregation ----------------
// 64 threads per node (4 channels each, float4); 4 nodes per 256-thread block
// PHASE 0: feat = g_h1;     out = g_hidden = relu(agg + b1)
// PHASE 1: feat = g_hidden; out = g_h1 (agg2, no bias)
template<int PHASE>
__global__ __launch_bounds__(256) void k_gather(const float* __restrict__ b1) {
    int node = (blockIdx.x << 2) + (threadIdx.x >> 6);
    if (node >= NN) return;
    int c = (threadIdx.x & 63) << 2;
    const float* feat = (PHASE == 0) ? g_h1 : g_hidden;

    float ds = g_dis[node];
    float dsq = ds * ds;
    float4 acc = *reinterpret_cast<const float4*>(feat + (size_t)node * HID_D + c);
    acc.x *= dsq; acc.y *= dsq; acc.z *= dsq; acc.w *= dsq;

    int beg = g_rowptr[node];
    int end = g_rowptr[node + 1];
    int j = beg;
    for (; j + 1 < end; j += 2) {
        int   s0 = __ldg(&g_srcs[j]);
        int   s1 = __ldg(&g_srcs[j + 1]);
        float n0 = __ldg(&g_nrm2[j]);
        float n1 = __ldg(&g_nrm2[j + 1]);
        float4 v0 = *reinterpret_cast<const float4*>(feat + (size_t)s0 * HID_D + c);
        float4 v1 = *reinterpret_cast<const float4*>(feat + (size_t)s1 * HID_D + c);
        acc.x = fmaf(v0.x, n0, acc.x); acc.y = fmaf(v0.y, n0, acc.y);
        acc.z = fmaf(v0.z, n0, acc.z); acc.w = fmaf(v0.w, n0, acc.w);
        acc.x = fmaf(v1.x, n1, acc.x); acc.y = fmaf(v1.y, n1, acc.y);
        acc.z = fmaf(v1.z, n1, acc.z); acc.w = fmaf(v1.w, n1, acc.w);
    }
    if (j < end) {
        int   s0 = __ldg(&g_srcs[j]);
        float n0 = __ldg(&g_nrm2[j]);
        float4 v0 = *reinterpret_cast<const float4*>(feat + (size_t)s0 * HID_D + c);
        acc.x = fmaf(v0.x, n0, acc.x); acc.y = fmaf(v0.y, n0, acc.y);
        acc.z = fmaf(v0.z, n0, acc.z); acc.w = fmaf(v0.w, n0, acc.w);
    }

    if (PHASE == 0) {
        float4 bb = *reinterpret_cast<const float4*>(b1 + c);
        float4 h;
        h.x = fmaxf(acc.x + bb.x, 0.0f);
        h.y = fmaxf(acc.y + bb.y, 0.0f);
        h.z = fmaxf(acc.z + bb.z, 0.0f);
        h.w = fmaxf(acc.w + bb.w, 0.0f);
        *reinterpret_cast<float4*>(g_hidden + (size_t)node * HID_D + c) = h;
    } else {
        *reinterpret_cast<float4*>(g_h1 + (size_t)node * HID_D + c) = acc;
    }
}

// ---------------- GEMM: 128x128 tile, BK=8, 256 threads, f32x2 8x8 microtile ----------------
// MODE 0: g_h1[NN,256] = X[NN,512] @ W1[512,256]                 grid(2, 391)
// MODE 1: out[NN,128]x2 = g_h1[NN,256] @ {Wmu,Wlv} + {bmu,blv}   grid(2, 391)
template<int MODE>
__global__ __launch_bounds__(256) void k_gemm(
    const float* __restrict__ X,   const float* __restrict__ W1,
    const float* __restrict__ Wmu, const float* __restrict__ bmu,
    const float* __restrict__ Wlv, const float* __restrict__ blv,
    float* __restrict__ out)
{
    const float* A;
    const float* B;
    const float* bias;
    float* C;
    int K, ldb, ldc, nBase;
    if (MODE == 0) {
        A = X; B = W1; bias = nullptr; C = g_h1;
        K = IN_D; ldb = HID_D; ldc = HID_D; nBase = blockIdx.x * 128;
    } else {
        A = g_h1;
        B    = blockIdx.x ? Wlv : Wmu;
        bias = blockIdx.x ? blv : bmu;
        C = out + (size_t)blockIdx.x * NN * LAT_D;
        K = HID_D; ldb = LAT_D; ldc = LAT_D; nBase = 0;
    }
    const int M = NN;

    __shared__ float As[8][132];  // [k][m], padded; 132*4=528B rows (16B aligned)
    __shared__ float Bs[8][128];  // [k][n]

    int tid = threadIdx.x;
    int tx = tid & 15;            // n quad
    int ty = tid >> 4;            // m octet (8 contiguous rows)
    int mBase = blockIdx.y * 128;

    u64 accp[4][8];               // [m-pair][n] ; pair = (even m lo, odd m hi)
    #pragma unroll
    for (int p = 0; p < 4; p++)
        #pragma unroll
        for (int q = 0; q < 8; q++) accp[p][q] = 0ULL;

    for (int k0 = 0; k0 < K; k0 += 8) {
        // A tile 128x8
        {
            int ar = tid >> 1;
            int ac = (tid & 1) << 2;
            int grow = mBase + ar;
            float4 v = make_float4(0.f, 0.f, 0.f, 0.f);
            if (grow < M)
                v = *reinterpret_cast<const float4*>(A + (size_t)grow * K + k0 + ac);
            As[ac + 0][ar] = v.x;
            As[ac + 1][ar] = v.y;
            As[ac + 2][ar] = v.z;
            As[ac + 3][ar] = v.w;
        }
        // B tile 8x128
        {
            int kr = tid >> 5;
            int bc = (tid & 31) << 2;
            float4 v = *reinterpret_cast<const float4*>(B + (size_t)(k0 + kr) * ldb + nBase + bc);
            *reinterpret_cast<float4*>(&Bs[kr][bc]) = v;
        }
        __syncthreads();

        #pragma unroll
        for (int kk = 0; kk < 8; kk++) {
            const u64* ap = reinterpret_cast<const u64*>(&As[kk][ty << 3]);
            u64 a0 = ap[0], a1 = ap[1], a2 = ap[2], a3 = ap[3];
            float4 b0f = *reinterpret_cast<const float4*>(&Bs[kk][tx << 2]);
            float4 b1f = *reinterpret_cast<const float4*>(&Bs[kk][64 + (tx << 2)]);
            u64 b[8];
            b[0] = bcast2(b0f.x); b[1] = bcast2(b0f.y);
            b[2] = bcast2(b0f.z); b[3] = bcast2(b0f.w);
            b[4] = bcast2(b1f.x); b[5] = bcast2(b1f.y);
            b[6] = bcast2(b1f.z); b[7] = bcast2(b1f.w);
            #pragma unroll
            for (int q = 0; q < 8; q++) {
                accp[0][q] = fma2(a0, b[q], accp[0][q]);
                accp[1][q] = fma2(a1, b[q], accp[1][q]);
                accp[2][q] = fma2(a2, b[q], accp[2][q]);
                accp[3][q] = fma2(a3, b[q], accp[3][q]);
            }
        }
        __syncthreads();
    }

    // epilogue
    float4 bb0 = make_float4(0.f, 0.f, 0.f, 0.f);
    float4 bb1 = make_float4(0.f, 0.f, 0.f, 0.f);
    if (MODE == 1) {
        bb0 = *reinterpret_cast<const float4*>(bias + (tx << 2));
        bb1 = *reinterpret_cast<const float4*>(bias + 64 + (tx << 2));
    }

    #pragma unroll
    for (int p = 0; p < 4; p++) {
        int r0 = mBase + (ty << 3) + (p << 1);
        if (r0 < M) {
            float4 o0, o1;
            o0.x = lo2(accp[p][0]) + bb0.x; o0.y = lo2(accp[p][1]) + bb0.y;
            o0.z = lo2(accp[p][2]) + bb0.z; o0.w = lo2(accp[p][3]) + bb0.w;
            o1.x = lo2(accp[p][4]) + bb1.x; o1.y = lo2(accp[p][5]) + bb1.y;
            o1.z = lo2(accp[p][6]) + bb1.z; o1.w = lo2(accp[p][7]) + bb1.w;
            *reinterpret_cast<float4*>(C + (size_t)r0 * ldc + nBase + (tx << 2)) = o0;
            *reinterpret_cast<float4*>(C + (size_t)r0 * ldc + nBase + 64 + (tx << 2)) = o1;
        }
        int r1 = r0 + 1;
        if (r1 < M) {
            float4 o0, o1;
            o0.x = hi2(accp[p][0]) + bb0.x; o0.y = hi2(accp[p][1]) + bb0.y;
            o0.z = hi2(accp[p][2]) + bb0.z; o0.w = hi2(accp[p][3]) + bb0.w;
            o1.x = hi2(accp[p][4]) + bb1.x; o1.y = hi2(accp[p][5]) + bb1.y;
            o1.z = hi2(accp[p][6]) + bb1.z; o1.w = hi2(accp[p][7]) + bb1.w;
            *reinterpret_cast<float4*>(C + (size_t)r1 * ldc + nBase + (tx << 2)) = o0;
            *reinterpret_cast<float4*>(C + (size_t)r1 * ldc + nBase + 64 + (tx << 2)) = o1;
        }
    }
}

// ---------------- launch ----------------
extern "C" void kernel_launch(void* const* d_in, const int* in_sizes, int n_in,
                              void* d_out, int out_size) {
    const float* x   = (const float*)d_in[0];
    const int*   ei  = (const int*)d_in[1];     // [2, E] int32
    const float* ea  = (const float*)d_in[2];
    const float* W1  = (const float*)d_in[3];
    const float* b1  = (const float*)d_in[4];
    const float* Wmu = (const float*)d_in[5];
    const float* bmu = (const float*)d_in[6];
    const float* Wlv = (const float*)d_in[7];
    const float* blv = (const float*)d_in[8];
    float* out = (float*)d_out;

    const int TB = 256;
    int gN = (NN + TB - 1) / TB;
    int gE = (EE + TB - 1) / TB;

    // ---- GCN normalization ----
    k_init_deg <<<gN, TB>>>();
    k_deg_accum<<<gE, TB>>>(ei, ea);
    k_dis      <<<gN, TB>>>();
    k_norm     <<<gE, TB>>>(ei, ea);

    // ---- CSR build (counting sort by dst) ----
    k_zero_cnt<<<gN, TB>>>();
    k_hist    <<<gE, TB>>>(ei);
    k_scan1   <<<SCB, 256>>>();
    k_scan2   <<<1, 256>>>();
    k_scan3   <<<gN, TB>>>();
    k_fill    <<<gE, TB>>>(ei);

    // ---- conv1 transform: g_h1 = x @ W1 ----
    dim3 g1(2, (NN + 127) / 128);
    k_gemm<0><<<g1, 256>>>(x, W1, nullptr, nullptr, nullptr, nullptr, nullptr);

    // ---- aggregate conv1 (+bias+relu fused) -> g_hidden ----
    int gG = (NN + 3) / 4;
    k_gather<0><<<gG, 256>>>(b1);
    // ---- aggregate conv2 -> g_h1 ----
    k_gather<1><<<gG, 256>>>(b1);

    // ---- mu / logvar GEMMs fused in one launch ----
    dim3 g2(2, (NN + 127) / 128);
    k_gemm<1><<<g2, 256>>>(nullptr, nullptr, Wmu, bmu, Wlv, blv, out);
}

// round 8
// speedup vs baseline: 3.8900x; 1.5078x over previous
#include <cuda_runtime.h>
#include <cstddef>
#include <cstdint>

#define NN    50000
#define EE    800000
#define IN_D  512
#define HID_D 256
#define LAT_D 128
#define SCB   196      // ceil(NN/256) scan blocks
#define SPAD  132      // padded smem row (conflict-free)

typedef unsigned int u32;

// ---- static device scratch ----
__device__ __align__(16) float g_deg[NN];
__device__ __align__(16) float g_dis[NN];
__device__ __align__(16) float g_h1[(size_t)NN * HID_D];      // x@W1, later agg2
__device__ __align__(16) float g_hidden[(size_t)NN * HID_D];  // relu(agg1 + b1)
// CSR
__device__ int   g_cnt[NN];
__device__ int   g_rowptr[NN + 1];
__device__ int   g_bsum[256];
__device__ int   g_srcs[EE];
__device__ __align__(8) float g_nrm2[EE];

// ---------------- tf32 helpers ----------------
__device__ __forceinline__ u32 tf32r(float x) {
    u32 t;
    asm("cvt.rna.tf32.f32 %0, %1;" : "=r"(t) : "f"(x));
    return t;
}
__device__ __forceinline__ void mma8(float* d, const u32* a, const u32* b) {
    asm("mma.sync.aligned.m16n8k8.row.col.f32.tf32.tf32.f32 "
        "{%0,%1,%2,%3}, {%4,%5,%6,%7}, {%8,%9}, {%0,%1,%2,%3};"
        : "+f"(d[0]), "+f"(d[1]), "+f"(d[2]), "+f"(d[3])
        : "r"(a[0]), "r"(a[1]), "r"(a[2]), "r"(a[3]), "r"(b[0]), "r"(b[1]));
}

// ---------------- preprocessing ----------------
__global__ void k_init() {
    int i = blockIdx.x * blockDim.x + threadIdx.x;
    if (i < NN) { g_deg[i] = 1.0f; g_cnt[i] = 0; }
}
__global__ void k_deg_hist(const int* __restrict__ ei, const float* __restrict__ ea) {
    int e = blockIdx.x * blockDim.x + threadIdx.x;
    if (e < EE) {
        int d = ei[EE + e];
        atomicAdd(&g_deg[d], ea[e]);
        atomicAdd(&g_cnt[d], 1);
    }
}
__global__ void k_dis() {
    int i = blockIdx.x * blockDim.x + threadIdx.x;
    if (i < NN) {
        float d = g_deg[i];
        g_dis[i] = (d > 0.0f) ? rsqrtf(d) : 0.0f;
    }
}
__global__ void k_scan1() {
    __shared__ int s[256];
    int t = threadIdx.x;
    int i = blockIdx.x * 256 + t;
    int v = (i < NN) ? g_cnt[i] : 0;
    s[t] = v;
    #pragma unroll
    for (int off = 1; off < 256; off <<= 1) {
        __syncthreads();
        int add = (t >= off) ? s[t - off] : 0;
        __syncthreads();
        s[t] += add;
    }
    __syncthreads();
    if (i < NN) g_rowptr[i] = s[t] - v;
    if (t == 255) g_bsum[blockIdx.x] = s[255];
}
__global__ void k_scan2() {
    __shared__ int s[256];
    int t = threadIdx.x;
    int v = (t < SCB) ? g_bsum[t] : 0;
    s[t] = v;
    #pragma unroll
    for (int off = 1; off < 256; off <<= 1) {
        __syncthreads();
        int add = (t >= off) ? s[t - off] : 0;
        __syncthreads();
        s[t] += add;
    }
    __syncthreads();
    if (t < SCB) g_bsum[t] = s[t] - v;
}
__global__ void k_scan3() {
    int i = blockIdx.x * blockDim.x + threadIdx.x;
    if (i < NN) {
        int r = g_rowptr[i] + g_bsum[i >> 8];
        g_rowptr[i] = r;
        g_cnt[i] = r;   // running cursor for fill
    }
    if (i == 0) g_rowptr[NN] = EE;
}
__global__ void k_fill(const int* __restrict__ ei, const float* __restrict__ ea) {
    int e = blockIdx.x * blockDim.x + threadIdx.x;
    if (e < EE) {
        int s = ei[e];
        int d = ei[EE + e];
        int pos = atomicAdd(&g_cnt[d], 1);
        g_srcs[pos] = s;
        g_nrm2[pos] = g_dis[s] * ea[e] * g_dis[d];
    }
}

// ---------------- gather aggregation ----------------
// 64 threads per node (4 channels each, float4); 4 nodes per 256-thread block
// PHASE 0: feat = g_h1;     out = g_hidden = relu(agg + b1)
// PHASE 1: feat = g_hidden; out = g_h1 (agg2, no bias)
template<int PHASE>
__global__ __launch_bounds__(256) void k_gather(const float* __restrict__ b1) {
    int node = (blockIdx.x << 2) + (threadIdx.x >> 6);
    if (node >= NN) return;
    int c = (threadIdx.x & 63) << 2;
    const float* feat = (PHASE == 0) ? g_h1 : g_hidden;

    float ds = g_dis[node];
    float dsq = ds * ds;
    float4 acc = *reinterpret_cast<const float4*>(feat + (size_t)node * HID_D + c);
    acc.x *= dsq; acc.y *= dsq; acc.z *= dsq; acc.w *= dsq;

    int beg = g_rowptr[node];
    int end = g_rowptr[node + 1];
    int j = beg;
    for (; j + 1 < end; j += 2) {
        int   s0 = __ldg(&g_srcs[j]);
        int   s1 = __ldg(&g_srcs[j + 1]);
        float n0 = __ldg(&g_nrm2[j]);
        float n1 = __ldg(&g_nrm2[j + 1]);
        float4 v0 = *reinterpret_cast<const float4*>(feat + (size_t)s0 * HID_D + c);
        float4 v1 = *reinterpret_cast<const float4*>(feat + (size_t)s1 * HID_D + c);
        acc.x = fmaf(v0.x, n0, acc.x); acc.y = fmaf(v0.y, n0, acc.y);
        acc.z = fmaf(v0.z, n0, acc.z); acc.w = fmaf(v0.w, n0, acc.w);
        acc.x = fmaf(v1.x, n1, acc.x); acc.y = fmaf(v1.y, n1, acc.y);
        acc.z = fmaf(v1.z, n1, acc.z); acc.w = fmaf(v1.w, n1, acc.w);
    }
    if (j < end) {
        int   s0 = __ldg(&g_srcs[j]);
        float n0 = __ldg(&g_nrm2[j]);
        float4 v0 = *reinterpret_cast<const float4*>(feat + (size_t)s0 * HID_D + c);
        acc.x = fmaf(v0.x, n0, acc.x); acc.y = fmaf(v0.y, n0, acc.y);
        acc.z = fmaf(v0.z, n0, acc.z); acc.w = fmaf(v0.w, n0, acc.w);
    }

    if (PHASE == 0) {
        float4 bb = *reinterpret_cast<const float4*>(b1 + c);
        float4 h;
        h.x = fmaxf(acc.x + bb.x, 0.0f);
        h.y = fmaxf(acc.y + bb.y, 0.0f);
        h.z = fmaxf(acc.z + bb.z, 0.0f);
        h.w = fmaxf(acc.w + bb.w, 0.0f);
        *reinterpret_cast<float4*>(g_hidden + (size_t)node * HID_D + c) = h;
    } else {
        *reinterpret_cast<float4*>(g_h1 + (size_t)node * HID_D + c) = acc;
    }
}

// ---------------- tf32 tensor-core GEMM ----------------
// 128x128 block tile, BK=16, 256 threads (8 warps: 4 m x 2 n), warp tile 32x64
// MODE 0: g_h1[NN,256] = X[NN,512] @ W1[512,256]                 grid(2, 391)
// MODE 1: out[NN,128]x2 = g_h1[NN,256] @ {Wmu,Wlv} + {bmu,blv}   grid(2, 391)
template<int MODE>
__global__ __launch_bounds__(256) void k_gemm(
    const float* __restrict__ X,   const float* __restrict__ W1,
    const float* __restrict__ Wmu, const float* __restrict__ bmu,
    const float* __restrict__ Wlv, const float* __restrict__ blv,
    float* __restrict__ out)
{
    const float* A;
    const float* B;
    const float* bias;
    float* C;
    int K, ldb, ldc, nBase;
    if (MODE == 0) {
        A = X; B = W1; bias = nullptr; C = g_h1;
        K = IN_D; ldb = HID_D; ldc = HID_D; nBase = blockIdx.x * 128;
    } else {
        A = g_h1;
        B    = blockIdx.x ? Wlv : Wmu;
        bias = blockIdx.x ? blv : bmu;
        C = out + (size_t)blockIdx.x * NN * LAT_D;
        K = HID_D; ldb = LAT_D; ldc = LAT_D; nBase = 0;
    }
    const int M = NN;

    __shared__ u32 As[16][SPAD];   // [k][m] tf32
    __shared__ u32 Bs[16][SPAD];   // [k][n] tf32

    int tid = threadIdx.x;
    int lane = tid & 31;
    int wid = tid >> 5;
    int warp_m = wid >> 1;         // 0..3 -> 32 rows each
    int warp_n = wid & 1;          // 0..1 -> 64 cols each
    int g = lane >> 2;             // 0..7
    int l = lane & 3;              // 0..3
    int mBase = blockIdx.y * 128;

    float acc[2][8][4];
    #pragma unroll
    for (int mi = 0; mi < 2; mi++)
        #pragma unroll
        for (int ni = 0; ni < 8; ni++)
            #pragma unroll
            for (int q = 0; q < 4; q++) acc[mi][ni][q] = 0.0f;

    for (int k0 = 0; k0 < K; k0 += 16) {
        // A tile 128x16 -> As[k][m] (transposed store, tf32)
        #pragma unroll
        for (int rep = 0; rep < 2; rep++) {
            int lin = tid + rep * 256;
            int row = lin >> 2;
            int c4 = (lin & 3) << 2;
            int grow = mBase + row;
            float4 v = make_float4(0.f, 0.f, 0.f, 0.f);
            if (grow < M)
                v = *reinterpret_cast<const float4*>(A + (size_t)grow * K + k0 + c4);
            As[c4 + 0][row] = tf32r(v.x);
            As[c4 + 1][row] = tf32r(v.y);
            As[c4 + 2][row] = tf32r(v.z);
            As[c4 + 3][row] = tf32r(v.w);
        }
        // B tile 16x128 -> Bs[k][n] (tf32)
        #pragma unroll
        for (int rep = 0; rep < 2; rep++) {
            int lin = tid + rep * 256;
            int kr = lin >> 5;
            int c4 = (lin & 31) << 2;
            float4 v = *reinterpret_cast<const float4*>(B + (size_t)(k0 + kr) * ldb + nBase + c4);
            uint4 u;
            u.x = tf32r(v.x); u.y = tf32r(v.y); u.z = tf32r(v.z); u.w = tf32r(v.w);
            *reinterpret_cast<uint4*>(&Bs[kr][c4]) = u;
        }
        __syncthreads();

        #pragma unroll
        for (int ks = 0; ks < 16; ks += 8) {
            u32 af[2][4];
            #pragma unroll
            for (int mi = 0; mi < 2; mi++) {
                int am = warp_m * 32 + mi * 16;
                af[mi][0] = As[ks + l][am + g];
                af[mi][1] = As[ks + l][am + g + 8];
                af[mi][2] = As[ks + l + 4][am + g];
                af[mi][3] = As[ks + l + 4][am + g + 8];
            }
            u32 bf[8][2];
            #pragma unroll
            for (int ni = 0; ni < 8; ni++) {
                int bn = warp_n * 64 + ni * 8;
                bf[ni][0] = Bs[ks + l][bn + g];
                bf[ni][1] = Bs[ks + l + 4][bn + g];
            }
            #pragma unroll
            for (int mi = 0; mi < 2; mi++)
                #pragma unroll
                for (int ni = 0; ni < 8; ni++)
                    mma8(acc[mi][ni], af[mi], bf[ni]);
        }
        __syncthreads();
    }

    // epilogue: thread holds rows (g, g+8), cols (2l, 2l+1) per tile
    #pragma unroll
    for (int mi = 0; mi < 2; mi++) {
        int r0 = mBase + warp_m * 32 + mi * 16 + g;
        int r1 = r0 + 8;
        #pragma unroll
        for (int ni = 0; ni < 8; ni++) {
            int col = nBase + warp_n * 64 + ni * 8 + (l << 1);
            float2 bb = make_float2(0.f, 0.f);
            if (MODE == 1) bb = *reinterpret_cast<const float2*>(bias + col);
            if (r0 < M) {
                float2 o;
                o.x = acc[mi][ni][0] + bb.x;
                o.y = acc[mi][ni][1] + bb.y;
                *reinterpret_cast<float2*>(C + (size_t)r0 * ldc + col) = o;
            }
            if (r1 < M) {
                float2 o;
                o.x = acc[mi][ni][2] + bb.x;
                o.y = acc[mi][ni][3] + bb.y;
                *reinterpret_cast<float2*>(C + (size_t)r1 * ldc + col) = o;
            }
        }
    }
}

// ---------------- launch ----------------
extern "C" void kernel_launch(void* const* d_in, const int* in_sizes, int n_in,
                              void* d_out, int out_size) {
    const float* x   = (const float*)d_in[0];
    const int*   ei  = (const int*)d_in[1];     // [2, E] int32
    const float* ea  = (const float*)d_in[2];
    const float* W1  = (const float*)d_in[3];
    const float* b1  = (const float*)d_in[4];
    const float* Wmu = (const float*)d_in[5];
    const float* bmu = (const float*)d_in[6];
    const float* Wlv = (const float*)d_in[7];
    const float* blv = (const float*)d_in[8];
    float* out = (float*)d_out;

    const int TB = 256;
    int gN = (NN + TB - 1) / TB;
    int gE = (EE + TB - 1) / TB;

    // ---- normalization + CSR build ----
    k_init    <<<gN, TB>>>();
    k_deg_hist<<<gE, TB>>>(ei, ea);
    k_dis     <<<gN, TB>>>();
    k_scan1   <<<SCB, 256>>>();
    k_scan2   <<<1, 256>>>();
    k_scan3   <<<gN, TB>>>();
    k_fill    <<<gE, TB>>>(ei, ea);

    // ---- conv1 transform: g_h1 = x @ W1 ----
    dim3 g1(2, (NN + 127) / 128);
    k_gemm<0><<<g1, 256>>>(x, W1, nullptr, nullptr, nullptr, nullptr, nullptr);

    // ---- aggregate conv1 (+bias+relu fused) -> g_hidden ----
    int gG = (NN + 3) / 4;
    k_gather<0><<<gG, 256>>>(b1);
    // ---- aggregate conv2 -> g_h1 ----
    k_gather<1><<<gG, 256>>>(b1);

    // ---- mu / logvar GEMMs fused in one launch ----
    dim3 g2(2, (NN + 127) / 128);
    k_gemm<1><<<g2, 256>>>(nullptr, nullptr, Wmu, bmu, Wlv, blv, out);
}

// round 10
// speedup vs baseline: 4.6504x; 1.1955x over previous
#include <cuda_runtime.h>
#include <cstddef>
#include <cstdint>

#define NN    50000
#define EE    800000
#define IN_D  512
#define HID_D 256
#define LAT_D 128
#define SCB   196      // ceil(NN/256) scan blocks
#define APAD  20       // A smem row stride (floats): conflict-free + 16B aligned
#define BPAD  132      // B smem row stride (floats)

typedef unsigned int u32;

// ---- static device scratch ----
__device__ __align__(16) float g_deg[NN];
__device__ __align__(16) float g_dis[NN];
__device__ __align__(16) float g_h1[(size_t)NN * HID_D];      // x@W1, later agg2
__device__ __align__(16) float g_hidden[(size_t)NN * HID_D];  // relu(agg1 + b1)
// CSR
__device__ int   g_cnt[NN];
__device__ int   g_rowptr[NN + 1];
__device__ int   g_bsum[256];
__device__ int   g_srcs[EE];
__device__ __align__(8) float g_nrm2[EE];

// ---------------- tf32 / cp.async helpers ----------------
__device__ __forceinline__ u32 tf32r(float x) {
    u32 t;
    asm("cvt.rna.tf32.f32 %0, %1;" : "=r"(t) : "f"(x));
    return t;
}
__device__ __forceinline__ void mma8(float* d, const u32* a, const u32* b) {
    asm("mma.sync.aligned.m16n8k8.row.col.f32.tf32.tf32.f32 "
        "{%0,%1,%2,%3}, {%4,%5,%6,%7}, {%8,%9}, {%0,%1,%2,%3};"
        : "+f"(d[0]), "+f"(d[1]), "+f"(d[2]), "+f"(d[3])
        : "r"(a[0]), "r"(a[1]), "r"(a[2]), "r"(a[3]), "r"(b[0]), "r"(b[1]));
}
__device__ __forceinline__ void cpa16(u32 smem, const void* gp, int src_sz) {
    asm volatile("cp.async.ca.shared.global [%0], [%1], 16, %2;"
                 :: "r"(smem), "l"(gp), "r"(src_sz));
}
__device__ __forceinline__ void cpa_commit() {
    asm volatile("cp.async.commit_group;");
}
template<int N>
__device__ __forceinline__ void cpa_wait() {
    asm volatile("cp.async.wait_group %0;" :: "n"(N));
}

// ---------------- preprocessing ----------------
__global__ void k_init() {
    int i = blockIdx.x * blockDim.x + threadIdx.x;
    if (i < NN) { g_deg[i] = 1.0f; g_cnt[i] = 0; }
}
__global__ void k_deg_hist(const int* __restrict__ ei, const float* __restrict__ ea) {
    int e = blockIdx.x * blockDim.x + threadIdx.x;
    if (e < EE) {
        int d = ei[EE + e];
        atomicAdd(&g_deg[d], ea[e]);
        atomicAdd(&g_cnt[d], 1);
    }
}
__global__ void k_dis() {
    int i = blockIdx.x * blockDim.x + threadIdx.x;
    if (i < NN) {
        float d = g_deg[i];
        g_dis[i] = (d > 0.0f) ? rsqrtf(d) : 0.0f;
    }
}
__global__ void k_scan1() {
    __shared__ int s[256];
    int t = threadIdx.x;
    int i = blockIdx.x * 256 + t;
    int v = (i < NN) ? g_cnt[i] : 0;
    s[t] = v;
    #pragma unroll
    for (int off = 1; off < 256; off <<= 1) {
        __syncthreads();
        int add = (t >= off) ? s[t - off] : 0;
        __syncthreads();
        s[t] += add;
    }
    __syncthreads();
    if (i < NN) g_rowptr[i] = s[t] - v;
    if (t == 255) g_bsum[blockIdx.x] = s[255];
}
__global__ void k_scan2() {
    __shared__ int s[256];
    int t = threadIdx.x;
    int v = (t < SCB) ? g_bsum[t] : 0;
    s[t] = v;
    #pragma unroll
    for (int off = 1; off < 256; off <<= 1) {
        __syncthreads();
        int add = (t >= off) ? s[t - off] : 0;
        __syncthreads();
        s[t] += add;
    }
    __syncthreads();
    if (t < SCB) g_bsum[t] = s[t] - v;
}
__global__ void k_scan3() {
    int i = blockIdx.x * blockDim.x + threadIdx.x;
    if (i < NN) {
        int r = g_rowptr[i] + g_bsum[i >> 8];
        g_rowptr[i] = r;
        g_cnt[i] = r;   // running cursor for fill
    }
    if (i == 0) g_rowptr[NN] = EE;
}
__global__ void k_fill(const int* __restrict__ ei, const float* __restrict__ ea) {
    int e = blockIdx.x * blockDim.x + threadIdx.x;
    if (e < EE) {
        int s = ei[e];
        int d = ei[EE + e];
        int pos = atomicAdd(&g_cnt[d], 1);
        g_srcs[pos] = s;
        g_nrm2[pos] = g_dis[s] * ea[e] * g_dis[d];
    }
}

// ---------------- gather aggregation ----------------
// 64 threads per node (4 channels each, float4); 4 nodes per 256-thread block
// PHASE 0: feat = g_h1;     out = g_hidden = relu(agg + b1)
// PHASE 1: feat = g_hidden; out = g_h1 (agg2, no bias)
template<int PHASE>
__global__ __launch_bounds__(256) void k_gather(const float* __restrict__ b1) {
    int node = (blockIdx.x << 2) + (threadIdx.x >> 6);
    if (node >= NN) return;
    int c = (threadIdx.x & 63) << 2;
    const float* feat = (PHASE == 0) ? g_h1 : g_hidden;

    float ds = g_dis[node];
    float dsq = ds * ds;
    float4 acc = *reinterpret_cast<const float4*>(feat + (size_t)node * HID_D + c);
    acc.x *= dsq; acc.y *= dsq; acc.z *= dsq; acc.w *= dsq;

    int beg = g_rowptr[node];
    int end = g_rowptr[node + 1];
    int j = beg;
    for (; j + 1 < end; j += 2) {
        int   s0 = __ldg(&g_srcs[j]);
        int   s1 = __ldg(&g_srcs[j + 1]);
        float n0 = __ldg(&g_nrm2[j]);
        float n1 = __ldg(&g_nrm2[j + 1]);
        float4 v0 = *reinterpret_cast<const float4*>(feat + (size_t)s0 * HID_D + c);
        float4 v1 = *reinterpret_cast<const float4*>(feat + (size_t)s1 * HID_D + c);
        acc.x = fmaf(v0.x, n0, acc.x); acc.y = fmaf(v0.y, n0, acc.y);
        acc.z = fmaf(v0.z, n0, acc.z); acc.w = fmaf(v0.w, n0, acc.w);
        acc.x = fmaf(v1.x, n1, acc.x); acc.y = fmaf(v1.y, n1, acc.y);
        acc.z = fmaf(v1.z, n1, acc.z); acc.w = fmaf(v1.w, n1, acc.w);
    }
    if (j < end) {
        int   s0 = __ldg(&g_srcs[j]);
        float n0 = __ldg(&g_nrm2[j]);
        float4 v0 = *reinterpret_cast<const float4*>(feat + (size_t)s0 * HID_D + c);
        acc.x = fmaf(v0.x, n0, acc.x); acc.y = fmaf(v0.y, n0, acc.y);
        acc.z = fmaf(v0.z, n0, acc.z); acc.w = fmaf(v0.w, n0, acc.w);
    }

    if (PHASE == 0) {
        float4 bb = *reinterpret_cast<const float4*>(b1 + c);
        float4 h;
        h.x = fmaxf(acc.x + bb.x, 0.0f);
        h.y = fmaxf(acc.y + bb.y, 0.0f);
        h.z = fmaxf(acc.z + bb.z, 0.0f);
        h.w = fmaxf(acc.w + bb.w, 0.0f);
        *reinterpret_cast<float4*>(g_hidden + (size_t)node * HID_D + c) = h;
    } else {
        *reinterpret_cast<float4*>(g_h1 + (size_t)node * HID_D + c) = acc;
    }
}

// ---------------- tf32 tensor-core GEMM, cp.async double-buffered ----------------
// 128x128 block tile, BK=16, 256 threads (8 warps: 4 m x 2 n), warp tile 32x64
// MODE 0: g_h1[NN,256] = X[NN,512] @ W1[512,256]                 grid(2, 391)
// MODE 1: out[NN,128]x2 = g_h1[NN,256] @ {Wmu,Wlv} + {bmu,blv}   grid(2, 391)
template<int MODE>
__global__ __launch_bounds__(256) void k_gemm(
    const float* __restrict__ X,   const float* __restrict__ W1,
    const float* __restrict__ Wmu, const float* __restrict__ bmu,
    const float* __restrict__ Wlv, const float* __restrict__ blv,
    float* __restrict__ out)
{
    const float* A;
    const float* B;
    const float* bias;
    float* C;
    int K, ldb, ldc, nBase;
    if (MODE == 0) {
        A = X; B = W1; bias = nullptr; C = g_h1;
        K = IN_D; ldb = HID_D; ldc = HID_D; nBase = blockIdx.x * 128;
    } else {
        A = g_h1;
        B    = blockIdx.x ? Wlv : Wmu;
        bias = blockIdx.x ? blv : bmu;
        C = out + (size_t)blockIdx.x * NN * LAT_D;
        K = HID_D; ldb = LAT_D; ldc = LAT_D; nBase = 0;
    }
    const int M = NN;

    __shared__ float As[2][128][APAD];   // [stage][m][k]  raw fp32
    __shared__ float Bs[2][16][BPAD];    // [stage][k][n]  raw fp32

    int tid = threadIdx.x;
    int lane = tid & 31;
    int wid = tid >> 5;
    int warp_m = wid >> 1;         // 0..3 -> 32 rows each
    int warp_n = wid & 1;          // 0..1 -> 64 cols each
    int g = lane >> 2;             // 0..7
    int l = lane & 3;              // 0..3
    int mBase = blockIdx.y * 128;

    // per-thread copy coordinates (2 x 16B for A, 2 x 16B for B per tile)
    int a_row0 = tid >> 2;                  // 0..63
    int a_row1 = a_row0 + 64;               // 64..127
    int a_cq   = (tid & 3) << 2;            // k offset 0,4,8,12
    int b_kr0  = tid >> 5;                  // 0..7
    int b_kr1  = b_kr0 + 8;                 // 8..15
    int b_cq   = (tid & 31) << 2;           // n offset 0..124

    u32 sA = (u32)__cvta_generic_to_shared(&As[0][0][0]);
    u32 sB = (u32)__cvta_generic_to_shared(&Bs[0][0][0]);
    const u32 A_STG = 128 * APAD * 4;
    const u32 B_STG = 16 * BPAD * 4;

    int a_sz0 = (mBase + a_row0 < M) ? 16 : 0;
    int a_sz1 = (mBase + a_row1 < M) ? 16 : 0;

    const int KT = K >> 4;

    // prologue: stage 0 <- tile 0
    {
        cpa16(sA + (a_row0 * APAD + a_cq) * 4, A + (size_t)(mBase + a_row0) * K + a_cq, a_sz0);
        cpa16(sA + (a_row1 * APAD + a_cq) * 4, A + (size_t)(mBase + a_row1) * K + a_cq, a_sz1);
        cpa16(sB + (b_kr0 * BPAD + b_cq) * 4, B + (size_t)b_kr0 * ldb + nBase + b_cq, 16);
        cpa16(sB + (b_kr1 * BPAD + b_cq) * 4, B + (size_t)b_kr1 * ldb + nBase + b_cq, 16);
        cpa_commit();
    }

    float acc[2][8][4];
    #pragma unroll
    for (int mi = 0; mi < 2; mi++)
        #pragma unroll
        for (int ni = 0; ni < 8; ni++)
            #pragma unroll
            for (int q = 0; q < 4; q++) acc[mi][ni][q] = 0.0f;

    for (int kt = 0; kt < KT; kt++) {
        int st = kt & 1;
        if (kt + 1 < KT) {
            int ns = (kt + 1) & 1;
            int k0 = (kt + 1) << 4;
            cpa16(sA + ns * A_STG + (a_row0 * APAD + a_cq) * 4,
                  A + (size_t)(mBase + a_row0) * K + k0 + a_cq, a_sz0);
            cpa16(sA + ns * A_STG + (a_row1 * APAD + a_cq) * 4,
                  A + (size_t)(mBase + a_row1) * K + k0 + a_cq, a_sz1);
            cpa16(sB + ns * B_STG + (b_kr0 * BPAD + b_cq) * 4,
                  B + (size_t)(k0 + b_kr0) * ldb + nBase + b_cq, 16);
            cpa16(sB + ns * B_STG + (b_kr1 * BPAD + b_cq) * 4,
                  B + (size_t)(k0 + b_kr1) * ldb + nBase + b_cq, 16);
            cpa_commit();
            cpa_wait<1>();
        } else {
            cpa_wait<0>();
        }
        __syncthreads();

        #pragma unroll
        for (int ks = 0; ks < 16; ks += 8) {
            u32 af[2][4];
            #pragma unroll
            for (int mi = 0; mi < 2; mi++) {
                int am = warp_m * 32 + mi * 16;
                af[mi][0] = tf32r(As[st][am + g][ks + l]);
                af[mi][1] = tf32r(As[st][am + g + 8][ks + l]);
                af[mi][2] = tf32r(As[st][am + g][ks + l + 4]);
                af[mi][3] = tf32r(As[st][am + g + 8][ks + l + 4]);
            }
            u32 bf[8][2];
            #pragma unroll
            for (int ni = 0; ni < 8; ni++) {
                int bn = warp_n * 64 + ni * 8;
                bf[ni][0] = tf32r(Bs[st][ks + l][bn + g]);
                bf[ni][1] = tf32r(Bs[st][ks + l + 4][bn + g]);
            }
            #pragma unroll
            for (int mi = 0; mi < 2; mi++)
                #pragma unroll
                for (int ni = 0; ni < 8; ni++)
                    mma8(acc[mi][ni], af[mi], bf[ni]);
        }
        __syncthreads();
    }

    // epilogue: thread holds rows (g, g+8), cols (2l, 2l+1) per tile
    #pragma unroll
    for (int mi = 0; mi < 2; mi++) {
        int r0 = mBase + warp_m * 32 + mi * 16 + g;
        int r1 = r0 + 8;
        #pragma unroll
        for (int ni = 0; ni < 8; ni++) {
            int col = nBase + warp_n * 64 + ni * 8 + (l << 1);
            float2 bb = make_float2(0.f, 0.f);
            if (MODE == 1) bb = *reinterpret_cast<const float2*>(bias + col);
            if (r0 < M) {
                float2 o;
                o.x = acc[mi][ni][0] + bb.x;
                o.y = acc[mi][ni][1] + bb.y;
                *reinterpret_cast<float2*>(C + (size_t)r0 * ldc + col) = o;
            }
            if (r1 < M) {
                float2 o;
                o.x = acc[mi][ni][2] + bb.x;
                o.y = acc[mi][ni][3] + bb.y;
                *reinterpret_cast<float2*>(C + (size_t)r1 * ldc + col) = o;
            }
        }
    }
}

// ---------------- launch ----------------
extern "C" void kernel_launch(void* const* d_in, const int* in_sizes, int n_in,
                              void* d_out, int out_size) {
    const float* x   = (const float*)d_in[0];
    const int*   ei  = (const int*)d_in[1];     // [2, E] int32
    const float* ea  = (const float*)d_in[2];
    const float* W1  = (const float*)d_in[3];
    const float* b1  = (const float*)d_in[4];
    const float* Wmu = (const float*)d_in[5];
    const float* bmu = (const float*)d_in[6];
    const float* Wlv = (const float*)d_in[7];
    const float* blv = (const float*)d_in[8];
    float* out = (float*)d_out;

    const int TB = 256;
    int gN = (NN + TB - 1) / TB;
    int gE = (EE + TB - 1) / TB;

    // ---- normalization + CSR build ----
    k_init    <<<gN, TB>>>();
    k_deg_hist<<<gE, TB>>>(ei, ea);
    k_dis     <<<gN, TB>>>();
    k_scan1   <<<SCB, 256>>>();
    k_scan2   <<<1, 256>>>();
    k_scan3   <<<gN, TB>>>();
    k_fill    <<<gE, TB>>>(ei, ea);

    // ---- conv1 transform: g_h1 = x @ W1 ----
    dim3 g1(2, (NN + 127) / 128);
    k_gemm<0><<<g1, 256>>>(x, W1, nullptr, nullptr, nullptr, nullptr, nullptr);

    // ---- aggregate conv1 (+bias+relu fused) -> g_hidden ----
    int gG = (NN + 3) / 4;
    k_gather<0><<<gG, 256>>>(b1);
    // ---- aggregate conv2 -> g_h1 ----
    k_gather<1><<<gG, 256>>>(b1);

    // ---- mu / logvar GEMMs fused in one launch ----
    dim3 g2(2, (NN + 127) / 128);
    k_gemm<1><<<g2, 256>>>(nullptr, nullptr, Wmu, bmu, Wlv, blv, out);
}

// round 11
// speedup vs baseline: 5.8504x; 1.2581x over previous
#include <cuda_runtime.h>
#include <cuda_fp16.h>
#include <cstddef>
#include <cstdint>

#define NN    50000
#define EE    800000
#define IN_D  512
#define HID_D 256
#define LAT_D 128
#define SCB   196      // ceil(NN/256) scan blocks
#define APAD  20       // A smem row stride (floats)
#define BPAD  132      // B smem row stride (floats)
#define G1BLK 782      // gemm1 blocks in fat kernel (2 x 391)

typedef unsigned int u32;

// ---- static device scratch ----
__device__ __align__(16) float  g_deg[NN];
__device__ __align__(16) float  g_dis[NN];
__device__ __align__(16) __half g_h1f[(size_t)NN * HID_D];    // x@W1 (fp16)
__device__ __align__(16) __half g_hidf[(size_t)NN * HID_D];   // relu(agg1+b1) (fp16)
__device__ __align__(16) float  g_agg[(size_t)NN * HID_D];    // agg2 (fp32)
// CSR
__device__ int   g_cnt[NN];
__device__ int   g_rowptr[NN + 1];
__device__ int   g_bsum[256];
__device__ int   g_srcs[EE];
__device__ __align__(8) float g_nrm2[EE];

// ---------------- tf32 / cp.async helpers ----------------
__device__ __forceinline__ u32 tf32r(float x) {
    u32 t;
    asm("cvt.rna.tf32.f32 %0, %1;" : "=r"(t) : "f"(x));
    return t;
}
__device__ __forceinline__ void mma8(float* d, const u32* a, const u32* b) {
    asm("mma.sync.aligned.m16n8k8.row.col.f32.tf32.tf32.f32 "
        "{%0,%1,%2,%3}, {%4,%5,%6,%7}, {%8,%9}, {%0,%1,%2,%3};"
        : "+f"(d[0]), "+f"(d[1]), "+f"(d[2]), "+f"(d[3])
        : "r"(a[0]), "r"(a[1]), "r"(a[2]), "r"(a[3]), "r"(b[0]), "r"(b[1]));
}
__device__ __forceinline__ void cpa16(u32 smem, const void* gp, int src_sz) {
    asm volatile("cp.async.ca.shared.global [%0], [%1], 16, %2;"
                 :: "r"(smem), "l"(gp), "r"(src_sz));
}
__device__ __forceinline__ void cpa_commit() {
    asm volatile("cp.async.commit_group;");
}
template<int N>
__device__ __forceinline__ void cpa_wait() {
    asm volatile("cp.async.wait_group %0;" :: "n"(N));
}
__device__ __forceinline__ void unpack8(uint4 u, float* v) {
    float2 f0 = __half22float2(*reinterpret_cast<__half2*>(&u.x));
    float2 f1 = __half22float2(*reinterpret_cast<__half2*>(&u.y));
    float2 f2 = __half22float2(*reinterpret_cast<__half2*>(&u.z));
    float2 f3 = __half22float2(*reinterpret_cast<__half2*>(&u.w));
    v[0] = f0.x; v[1] = f0.y; v[2] = f1.x; v[3] = f1.y;
    v[4] = f2.x; v[5] = f2.y; v[6] = f3.x; v[7] = f3.y;
}

// ---------------- preprocessing ----------------
__global__ void k_init() {
    int i = blockIdx.x * blockDim.x + threadIdx.x;
    if (i < NN) { g_deg[i] = 1.0f; g_cnt[i] = 0; }
}
__global__ void k_deg_hist(const int* __restrict__ ei, const float* __restrict__ ea) {
    int e = blockIdx.x * blockDim.x + threadIdx.x;
    if (e < EE) {
        int d = ei[EE + e];
        atomicAdd(&g_deg[d], ea[e]);
        atomicAdd(&g_cnt[d], 1);
    }
}
__global__ void k_dis() {
    int i = blockIdx.x * blockDim.x + threadIdx.x;
    if (i < NN) {
        float d = g_deg[i];
        g_dis[i] = (d > 0.0f) ? rsqrtf(d) : 0.0f;
    }
}
__global__ void k_scan1() {
    __shared__ int s[256];
    int t = threadIdx.x;
    int i = blockIdx.x * 256 + t;
    int v = (i < NN) ? g_cnt[i] : 0;
    s[t] = v;
    #pragma unroll
    for (int off = 1; off < 256; off <<= 1) {
        __syncthreads();
        int add = (t >= off) ? s[t - off] : 0;
        __syncthreads();
        s[t] += add;
    }
    __syncthreads();
    if (i < NN) g_rowptr[i] = s[t] - v;
    if (t == 255) g_bsum[blockIdx.x] = s[255];
}
__global__ void k_scan2() {
    __shared__ int s[256];
    int t = threadIdx.x;
    int v = (t < SCB) ? g_bsum[t] : 0;
    s[t] = v;
    #pragma unroll
    for (int off = 1; off < 256; off <<= 1) {
        __syncthreads();
        int add = (t >= off) ? s[t - off] : 0;
        __syncthreads();
        s[t] += add;
    }
    __syncthreads();
    if (t < SCB) g_bsum[t] = s[t] - v;
}
__global__ void k_scan3() {
    int i = blockIdx.x * blockDim.x + threadIdx.x;
    if (i < NN) {
        int r = g_rowptr[i] + g_bsum[i >> 8];
        g_rowptr[i] = r;
        g_cnt[i] = r;   // running cursor for fill
    }
    if (i == 0) g_rowptr[NN] = EE;
}

// ---------------- tf32 GEMM body (128x128 tile, BK=16, cp.async x2 stages) ----------------
// MODE 0: g_h1f[NN,256](fp16) = X[NN,512] @ W1[512,256]
// MODE 1: out[NN,128]x2 = g_agg[NN,256] @ {Wmu,Wlv} + {bmu,blv}
template<int MODE>
__device__ __forceinline__ void gemm_body(
    int bx, int by,
    const float* __restrict__ X,   const float* __restrict__ W1,
    const float* __restrict__ Wmu, const float* __restrict__ bmu,
    const float* __restrict__ Wlv, const float* __restrict__ blv,
    float* __restrict__ out)
{
    const float* A;
    const float* B;
    const float* bias;
    float* C = nullptr;
    int K, ldb, nBase;
    if (MODE == 0) {
        A = X; B = W1; bias = nullptr;
        K = IN_D; ldb = HID_D; nBase = bx * 128;
    } else {
        A = g_agg;
        B    = bx ? Wlv : Wmu;
        bias = bx ? blv : bmu;
        C = out + (size_t)bx * NN * LAT_D;
        K = HID_D; ldb = LAT_D; nBase = 0;
    }
    const int M = NN;

    __shared__ float As[2][128][APAD];
    __shared__ float Bs[2][16][BPAD];

    int tid = threadIdx.x;
    int lane = tid & 31;
    int wid = tid >> 5;
    int warp_m = wid >> 1;
    int warp_n = wid & 1;
    int g = lane >> 2;
    int l = lane & 3;
    int mBase = by * 128;

    int a_row0 = tid >> 2;
    int a_row1 = a_row0 + 64;
    int a_cq   = (tid & 3) << 2;
    int b_kr0  = tid >> 5;
    int b_kr1  = b_kr0 + 8;
    int b_cq   = (tid & 31) << 2;

    u32 sA = (u32)__cvta_generic_to_shared(&As[0][0][0]);
    u32 sB = (u32)__cvta_generic_to_shared(&Bs[0][0][0]);
    const u32 A_STG = 128 * APAD * 4;
    const u32 B_STG = 16 * BPAD * 4;

    int a_sz0 = (mBase + a_row0 < M) ? 16 : 0;
    int a_sz1 = (mBase + a_row1 < M) ? 16 : 0;

    const int KT = K >> 4;

    cpa16(sA + (a_row0 * APAD + a_cq) * 4, A + (size_t)(mBase + a_row0) * K + a_cq, a_sz0);
    cpa16(sA + (a_row1 * APAD + a_cq) * 4, A + (size_t)(mBase + a_row1) * K + a_cq, a_sz1);
    cpa16(sB + (b_kr0 * BPAD + b_cq) * 4, B + (size_t)b_kr0 * ldb + nBase + b_cq, 16);
    cpa16(sB + (b_kr1 * BPAD + b_cq) * 4, B + (size_t)b_kr1 * ldb + nBase + b_cq, 16);
    cpa_commit();

    float acc[2][8][4];
    #pragma unroll
    for (int mi = 0; mi < 2; mi++)
        #pragma unroll
        for (int ni = 0; ni < 8; ni++)
            #pragma unroll
            for (int q = 0; q < 4; q++) acc[mi][ni][q] = 0.0f;

    for (int kt = 0; kt < KT; kt++) {
        int st = kt & 1;
        if (kt + 1 < KT) {
            int ns = (kt + 1) & 1;
            int k0 = (kt + 1) << 4;
            cpa16(sA + ns * A_STG + (a_row0 * APAD + a_cq) * 4,
                  A + (size_t)(mBase + a_row0) * K + k0 + a_cq, a_sz0);
            cpa16(sA + ns * A_STG + (a_row1 * APAD + a_cq) * 4,
                  A + (size_t)(mBase + a_row1) * K + k0 + a_cq, a_sz1);
            cpa16(sB + ns * B_STG + (b_kr0 * BPAD + b_cq) * 4,
                  B + (size_t)(k0 + b_kr0) * ldb + nBase + b_cq, 16);
            cpa16(sB + ns * B_STG + (b_kr1 * BPAD + b_cq) * 4,
                  B + (size_t)(k0 + b_kr1) * ldb + nBase + b_cq, 16);
            cpa_commit();
            cpa_wait<1>();
        } else {
            cpa_wait<0>();
        }
        __syncthreads();

        #pragma unroll
        for (int ks = 0; ks < 16; ks += 8) {
            u32 af[2][4];
            #pragma unroll
            for (int mi = 0; mi < 2; mi++) {
                int am = warp_m * 32 + mi * 16;
                af[mi][0] = tf32r(As[st][am + g][ks + l]);
                af[mi][1] = tf32r(As[st][am + g + 8][ks + l]);
                af[mi][2] = tf32r(As[st][am + g][ks + l + 4]);
                af[mi][3] = tf32r(As[st][am + g + 8][ks + l + 4]);
            }
            u32 bf[8][2];
            #pragma unroll
            for (int ni = 0; ni < 8; ni++) {
                int bn = warp_n * 64 + ni * 8;
                bf[ni][0] = tf32r(Bs[st][ks + l][bn + g]);
                bf[ni][1] = tf32r(Bs[st][ks + l + 4][bn + g]);
            }
            #pragma unroll
            for (int mi = 0; mi < 2; mi++)
                #pragma unroll
                for (int ni = 0; ni < 8; ni++)
                    mma8(acc[mi][ni], af[mi], bf[ni]);
        }
        __syncthreads();
    }

    // epilogue
    #pragma unroll
    for (int mi = 0; mi < 2; mi++) {
        int r0 = mBase + warp_m * 32 + mi * 16 + g;
        int r1 = r0 + 8;
        #pragma unroll
        for (int ni = 0; ni < 8; ni++) {
            int col = nBase + warp_n * 64 + ni * 8 + (l << 1);
            if (MODE == 0) {
                if (r0 < M)
                    *reinterpret_cast<__half2*>(g_h1f + (size_t)r0 * HID_D + col) =
                        __floats2half2_rn(acc[mi][ni][0], acc[mi][ni][1]);
                if (r1 < M)
                    *reinterpret_cast<__half2*>(g_h1f + (size_t)r1 * HID_D + col) =
                        __floats2half2_rn(acc[mi][ni][2], acc[mi][ni][3]);
            } else {
                float2 bb = *reinterpret_cast<const float2*>(bias + col);
                if (r0 < M) {
                    float2 o; o.x = acc[mi][ni][0] + bb.x; o.y = acc[mi][ni][1] + bb.y;
                    *reinterpret_cast<float2*>(C + (size_t)r0 * LAT_D + col) = o;
                }
                if (r1 < M) {
                    float2 o; o.x = acc[mi][ni][2] + bb.x; o.y = acc[mi][ni][3] + bb.y;
                    *reinterpret_cast<float2*>(C + (size_t)r1 * LAT_D + col) = o;
                }
            }
        }
    }
}

// ---------------- fat kernel: gemm1 blocks + CSR fill blocks ----------------
__global__ __launch_bounds__(256) void k_gemm1_fill(
    const float* __restrict__ X, const float* __restrict__ W1,
    const int* __restrict__ ei, const float* __restrict__ ea)
{
    if (blockIdx.x < G1BLK) {
        gemm_body<0>(blockIdx.x & 1, blockIdx.x >> 1, X, W1,
                     nullptr, nullptr, nullptr, nullptr, nullptr);
    } else {
        int e = (blockIdx.x - G1BLK) * 256 + threadIdx.x;
        if (e < EE) {
            int s = ei[e];
            int d = ei[EE + e];
            int pos = atomicAdd(&g_cnt[d], 1);
            g_srcs[pos] = s;
            g_nrm2[pos] = g_dis[s] * ea[e] * g_dis[d];
        }
    }
}

__global__ __launch_bounds__(256) void k_gemm2(
    const float* __restrict__ Wmu, const float* __restrict__ bmu,
    const float* __restrict__ Wlv, const float* __restrict__ blv,
    float* __restrict__ out)
{
    gemm_body<1>(blockIdx.x, blockIdx.y, nullptr, nullptr, Wmu, bmu, Wlv, blv, out);
}

// ---------------- gather aggregation (fp16 features, fp32 accumulate) ----------------
// 32 threads per node (8 channels each, 16B load); 8 nodes per 256-thread block
// PHASE 0: feat = g_h1f;  out = g_hidf = relu(agg + b1)  (fp16)
// PHASE 1: feat = g_hidf; out = g_agg (fp32)
template<int PHASE>
__global__ __launch_bounds__(256) void k_gather(const float* __restrict__ b1) {
    int node = (blockIdx.x << 3) + (threadIdx.x >> 5);
    if (node >= NN) return;
    int c = (threadIdx.x & 31) << 3;   // 8 contiguous channels
    const __half* feat = (PHASE == 0) ? g_h1f : g_hidf;

    float ds = g_dis[node];
    float dsq = ds * ds;
    float acc[8], v[8];
    {
        uint4 u = *reinterpret_cast<const uint4*>(feat + (size_t)node * HID_D + c);
        unpack8(u, v);
        #pragma unroll
        for (int i = 0; i < 8; i++) acc[i] = dsq * v[i];
    }

    int beg = g_rowptr[node];
    int end = g_rowptr[node + 1];
    int j = beg;
    for (; j + 1 < end; j += 2) {
        int   s0 = __ldg(&g_srcs[j]);
        int   s1 = __ldg(&g_srcs[j + 1]);
        float n0 = __ldg(&g_nrm2[j]);
        float n1 = __ldg(&g_nrm2[j + 1]);
        uint4 u0 = *reinterpret_cast<const uint4*>(feat + (size_t)s0 * HID_D + c);
        uint4 u1 = *reinterpret_cast<const uint4*>(feat + (size_t)s1 * HID_D + c);
        float w0[8], w1[8];
        unpack8(u0, w0);
        unpack8(u1, w1);
        #pragma unroll
        for (int i = 0; i < 8; i++) acc[i] = fmaf(w0[i], n0, acc[i]);
        #pragma unroll
        for (int i = 0; i < 8; i++) acc[i] = fmaf(w1[i], n1, acc[i]);
    }
    if (j < end) {
        int   s0 = __ldg(&g_srcs[j]);
        float n0 = __ldg(&g_nrm2[j]);
        uint4 u0 = *reinterpret_cast<const uint4*>(feat + (size_t)s0 * HID_D + c);
        float w0[8];
        unpack8(u0, w0);
        #pragma unroll
        for (int i = 0; i < 8; i++) acc[i] = fmaf(w0[i], n0, acc[i]);
    }

    if (PHASE == 0) {
        float4 bb0 = *reinterpret_cast<const float4*>(b1 + c);
        float4 bb1 = *reinterpret_cast<const float4*>(b1 + c + 4);
        float h[8];
        h[0] = fmaxf(acc[0] + bb0.x, 0.0f); h[1] = fmaxf(acc[1] + bb0.y, 0.0f);
        h[2] = fmaxf(acc[2] + bb0.z, 0.0f); h[3] = fmaxf(acc[3] + bb0.w, 0.0f);
        h[4] = fmaxf(acc[4] + bb1.x, 0.0f); h[5] = fmaxf(acc[5] + bb1.y, 0.0f);
        h[6] = fmaxf(acc[6] + bb1.z, 0.0f); h[7] = fmaxf(acc[7] + bb1.w, 0.0f);
        uint4 u;
        *reinterpret_cast<__half2*>(&u.x) = __floats2half2_rn(h[0], h[1]);
        *reinterpret_cast<__half2*>(&u.y) = __floats2half2_rn(h[2], h[3]);
        *reinterpret_cast<__half2*>(&u.z) = __floats2half2_rn(h[4], h[5]);
        *reinterpret_cast<__half2*>(&u.w) = __floats2half2_rn(h[6], h[7]);
        *reinterpret_cast<uint4*>(g_hidf + (size_t)node * HID_D + c) = u;
    } else {
        float4 o0 = make_float4(acc[0], acc[1], acc[2], acc[3]);
        float4 o1 = make_float4(acc[4], acc[5], acc[6], acc[7]);
        *reinterpret_cast<float4*>(g_agg + (size_t)node * HID_D + c) = o0;
        *reinterpret_cast<float4*>(g_agg + (size_t)node * HID_D + c + 4) = o1;
    }
}

// ---------------- launch ----------------
extern "C" void kernel_launch(void* const* d_in, const int* in_sizes, int n_in,
                              void* d_out, int out_size) {
    const float* x   = (const float*)d_in[0];
    const int*   ei  = (const int*)d_in[1];     // [2, E] int32
    const float* ea  = (const float*)d_in[2];
    const float* W1  = (const float*)d_in[3];
    const float* b1  = (const float*)d_in[4];
    const float* Wmu = (const float*)d_in[5];
    const float* bmu = (const float*)d_in[6];
    const float* Wlv = (const float*)d_in[7];
    const float* blv = (const float*)d_in[8];
    float* out = (float*)d_out;

    const int TB = 256;
    int gN = (NN + TB - 1) / TB;
    int gE = (EE + TB - 1) / TB;

    // ---- normalization + CSR counts ----
    k_init    <<<gN, TB>>>();
    k_deg_hist<<<gE, TB>>>(ei, ea);
    k_dis     <<<gN, TB>>>();
    k_scan1   <<<SCB, 256>>>();
    k_scan2   <<<1, 256>>>();
    k_scan3   <<<gN, TB>>>();

    // ---- fat: conv1 transform (tf32 -> fp16) + CSR fill, overlapped ----
    k_gemm1_fill<<<G1BLK + gE, 256>>>(x, W1, ei, ea);

    // ---- aggregate conv1 (+bias+relu fused, fp16 out) ----
    int gG = (NN + 7) / 8;
    k_gather<0><<<gG, 256>>>(b1);
    // ---- aggregate conv2 (fp32 out) ----
    k_gather<1><<<gG, 256>>>(b1);

    // ---- mu / logvar GEMMs ----
    dim3 g2(2, (NN + 127) / 128);
    k_gemm2<<<g2, 256>>>(Wmu, bmu, Wlv, blv, out);
}

// round 13
// speedup vs baseline: 7.0369x; 1.2028x over previous
#include <cuda_runtime.h>
#include <cuda_fp16.h>
#include <cstddef>
#include <cstdint>

#define NN    50000
#define EE    800000
#define IN_D  512
#define HID_D 256
#define LAT_D 128
#define SCB   196      // ceil(NN/256)
#define SSTR  40       // smem row stride in halves (80B: 16B-aligned, conflict-free)
#define CVX   12500    // x-convert blocks (NN*IN_D/8/256)
#define CVW   768      // weight-convert blocks (196608/256)
#define G1BLK 782      // gemm1 blocks (2 x 391)
#define G2BLK 782      // gemm2 blocks (2 x 391)

typedef unsigned int u32;

// ---- static device scratch (zero-init at load; reset at end of each call) ----
__device__ __align__(16) float  g_deg[NN];     // accumulates from 0; dis=rsqrt(deg+1)
__device__ __align__(16) float  g_dis[NN];
__device__ __align__(16) __half g_xh[(size_t)NN * IN_D];     // x fp16
__device__ __align__(16) __half g_w1t[HID_D * IN_D];         // W1^T  [256][512]
__device__ __align__(16) __half g_wmut[LAT_D * HID_D];       // Wmu^T [128][256]
__device__ __align__(16) __half g_wlvt[LAT_D * HID_D];       // Wlv^T [128][256]
__device__ __align__(16) __half g_h1f[(size_t)NN * HID_D];   // x@W1 (fp16)
__device__ __align__(16) __half g_hidf[(size_t)NN * HID_D];  // relu(agg1+b1) (fp16)
__device__ __align__(16) __half g_aggf[(size_t)NN * HID_D];  // agg2 (fp16)
// CSR
__device__ int   g_cnt[NN];
__device__ int   g_rowptr[NN + 1];
__device__ int   g_bsum[256];
__device__ int   g_srcs[EE];
__device__ __align__(8) float g_nrm2[EE];

// ---------------- helpers ----------------
__device__ __forceinline__ void mma16(float* d, const u32* a, const u32* b) {
    asm("mma.sync.aligned.m16n8k16.row.col.f32.f16.f16.f32 "
        "{%0,%1,%2,%3}, {%4,%5,%6,%7}, {%8,%9}, {%0,%1,%2,%3};"
        : "+f"(d[0]), "+f"(d[1]), "+f"(d[2]), "+f"(d[3])
        : "r"(a[0]), "r"(a[1]), "r"(a[2]), "r"(a[3]), "r"(b[0]), "r"(b[1]));
}
__device__ __forceinline__ void cpa16(u32 smem, const void* gp, int src_sz) {
    asm volatile("cp.async.ca.shared.global [%0], [%1], 16, %2;"
                 :: "r"(smem), "l"(gp), "r"(src_sz));
}
__device__ __forceinline__ void cpa_commit() {
    asm volatile("cp.async.commit_group;");
}
template<int N>
__device__ __forceinline__ void cpa_wait() {
    asm volatile("cp.async.wait_group %0;" :: "n"(N));
}
__device__ __forceinline__ void unpack8(uint4 u, float* v) {
    float2 f0 = __half22float2(*reinterpret_cast<__half2*>(&u.x));
    float2 f1 = __half22float2(*reinterpret_cast<__half2*>(&u.y));
    float2 f2 = __half22float2(*reinterpret_cast<__half2*>(&u.z));
    float2 f3 = __half22float2(*reinterpret_cast<__half2*>(&u.w));
    v[0] = f0.x; v[1] = f0.y; v[2] = f1.x; v[3] = f1.y;
    v[4] = f2.x; v[5] = f2.y; v[6] = f3.x; v[7] = f3.y;
}

// ---------------- fat prep: x->fp16  |  W transpose->fp16  |  deg/cnt hist ----------------
__global__ __launch_bounds__(256) void k_prep(
    const float* __restrict__ x, const float* __restrict__ W1,
    const float* __restrict__ Wmu, const float* __restrict__ Wlv,
    const int* __restrict__ ei, const float* __restrict__ ea)
{
    int b = blockIdx.x;
    if (b < CVX) {
        int idx = b * 256 + threadIdx.x;   // 8 halves per thread, exact coverage
        const float4* xp = reinterpret_cast<const float4*>(x);
        float4 f0 = xp[2 * idx];
        float4 f1 = xp[2 * idx + 1];
        uint4 u;
        *reinterpret_cast<__half2*>(&u.x) = __floats2half2_rn(f0.x, f0.y);
        *reinterpret_cast<__half2*>(&u.y) = __floats2half2_rn(f0.z, f0.w);
        *reinterpret_cast<__half2*>(&u.z) = __floats2half2_rn(f1.x, f1.y);
        *reinterpret_cast<__half2*>(&u.w) = __floats2half2_rn(f1.z, f1.w);
        reinterpret_cast<uint4*>(g_xh)[idx] = u;
    } else if (b < CVX + CVW) {
        int idx = (b - CVX) * 256 + threadIdx.x;
        if (idx < HID_D * IN_D) {                  // W1T[n][k] = W1[k][n]
            int n = idx >> 9, k = idx & 511;
            g_w1t[idx] = __float2half(W1[k * HID_D + n]);
        } else {
            int j = idx - HID_D * IN_D;            // 2 x 32768 for Wmu/Wlv
            int which = j >= LAT_D * HID_D;
            int jj = j - which * LAT_D * HID_D;
            int n = jj >> 8, k = jj & 255;
            const float* W = which ? Wlv : Wmu;
            (which ? g_wlvt : g_wmut)[jj] = __float2half(W[k * LAT_D + n]);
        }
    } else {
        int e = (b - CVX - CVW) * 256 + threadIdx.x;
        if (e < EE) {
            int d = ei[EE + e];
            atomicAdd(&g_deg[d], ea[e]);
            atomicAdd(&g_cnt[d], 1);
        }
    }
}

// ---------------- scans (scan1 also computes dis) ----------------
__global__ void k_scan1() {
    __shared__ int s[256];
    int t = threadIdx.x;
    int i = blockIdx.x * 256 + t;
    int v = (i < NN) ? g_cnt[i] : 0;
    if (i < NN) g_dis[i] = rsqrtf(g_deg[i] + 1.0f);   // self-loop weight 1
    s[t] = v;
    #pragma unroll
    for (int off = 1; off < 256; off <<= 1) {
        __syncthreads();
        int add = (t >= off) ? s[t - off] : 0;
        __syncthreads();
        s[t] += add;
    }
    __syncthreads();
    if (i < NN) g_rowptr[i] = s[t] - v;
    if (t == 255) g_bsum[blockIdx.x] = s[255];
}
__global__ void k_scan2() {
    __shared__ int s[256];
    int t = threadIdx.x;
    int v = (t < SCB) ? g_bsum[t] : 0;
    s[t] = v;
    #pragma unroll
    for (int off = 1; off < 256; off <<= 1) {
        __syncthreads();
        int add = (t >= off) ? s[t - off] : 0;
        __syncthreads();
        s[t] += add;
    }
    __syncthreads();
    if (t < SCB) g_bsum[t] = s[t] - v;
}
__global__ void k_scan3() {
    int i = blockIdx.x * blockDim.x + threadIdx.x;
    if (i < NN) {
        int r = g_rowptr[i] + g_bsum[i >> 8];
        g_rowptr[i] = r;
        g_cnt[i] = r;   // running cursor for fill
    }
    if (i == 0) g_rowptr[NN] = EE;
}

// ---------------- fp16 HMMA GEMM body (128x128 tile, BK=32, cp.async x2 stages) ----------------
// MODE 0: g_h1f[NN,256] = xh[NN,512] @ W1T^T        (bx = n-half, by = m-tile)
// MODE 1: out[NN,128] = aggf[NN,256] @ W?T^T + bias (bx = mu/lv,  by = m-tile)
template<int MODE>
__device__ __forceinline__ void gemm_body(
    int bx, int by, const float* __restrict__ bias, float* __restrict__ out)
{
    const __half* A;
    const __half* Bt;    // n-major [n][K]
    int K, nBase;
    if (MODE == 0) {
        A = g_xh; Bt = g_w1t; K = IN_D; nBase = bx * 128;
    } else {
        A = g_aggf; Bt = bx ? g_wlvt : g_wmut; K = HID_D; nBase = 0;
    }
    const int M = NN;

    __shared__ __half As[2][128][SSTR];
    __shared__ __half Bs[2][128][SSTR];

    int tid = threadIdx.x;
    int lane = tid & 31;
    int wid = tid >> 5;
    int warp_m = wid >> 1;
    int warp_n = wid & 1;
    int g = lane >> 2;
    int l = lane & 3;
    int mBase = by * 128;

    int c_row = tid >> 1;               // 0..127
    int c_off = (tid & 1) << 4;         // 0 or 16 halves

    u32 sA = (u32)__cvta_generic_to_shared(&As[0][0][0]);
    u32 sB = (u32)__cvta_generic_to_shared(&Bs[0][0][0]);
    const u32 STG = 128 * SSTR * 2;     // bytes per stage

    int a_sz = (mBase + c_row < M) ? 16 : 0;

    const int KT = K >> 5;

    // prologue
    cpa16(sA + (c_row * SSTR + c_off) * 2,     A + (size_t)(mBase + c_row) * K + c_off, a_sz);
    cpa16(sA + (c_row * SSTR + c_off + 8) * 2, A + (size_t)(mBase + c_row) * K + c_off + 8, a_sz);
    cpa16(sB + (c_row * SSTR + c_off) * 2,     Bt + (size_t)(nBase + c_row) * K + c_off, 16);
    cpa16(sB + (c_row * SSTR + c_off + 8) * 2, Bt + (size_t)(nBase + c_row) * K + c_off + 8, 16);
    cpa_commit();

    float acc[2][8][4];
    #pragma unroll
    for (int mi = 0; mi < 2; mi++)
        #pragma unroll
        for (int ni = 0; ni < 8; ni++)
            #pragma unroll
            for (int q = 0; q < 4; q++) acc[mi][ni][q] = 0.0f;

    for (int kt = 0; kt < KT; kt++) {
        int st = kt & 1;
        if (kt + 1 < KT) {
            int ns = (kt + 1) & 1;
            int k0 = (kt + 1) << 5;
            cpa16(sA + ns * STG + (c_row * SSTR + c_off) * 2,
                  A + (size_t)(mBase + c_row) * K + k0 + c_off, a_sz);
            cpa16(sA + ns * STG + (c_row * SSTR + c_off + 8) * 2,
                  A + (size_t)(mBase + c_row) * K + k0 + c_off + 8, a_sz);
            cpa16(sB + ns * STG + (c_row * SSTR + c_off) * 2,
                  Bt + (size_t)(nBase + c_row) * K + k0 + c_off, 16);
            cpa16(sB + ns * STG + (c_row * SSTR + c_off + 8) * 2,
                  Bt + (size_t)(nBase + c_row) * K + k0 + c_off + 8, 16);
            cpa_commit();
            cpa_wait<1>();
        } else {
            cpa_wait<0>();
        }
        __syncthreads();

        const u32* Au = reinterpret_cast<const u32*>(&As[st][0][0]);
        const u32* Bu = reinterpret_cast<const u32*>(&Bs[st][0][0]);
        const int RS = SSTR >> 1;   // 20 u32 per row

        #pragma unroll
        for (int ks = 0; ks < 2; ks++) {
            int ko = ks << 3;       // u32 k-offset
            u32 af[2][4];
            #pragma unroll
            for (int mi = 0; mi < 2; mi++) {
                int base = (warp_m * 32 + mi * 16 + g) * RS + ko + l;
                af[mi][0] = Au[base];
                af[mi][1] = Au[base + 8 * RS];
                af[mi][2] = Au[base + 4];
                af[mi][3] = Au[base + 8 * RS + 4];
            }
            u32 bf[8][2];
            #pragma unroll
            for (int ni = 0; ni < 8; ni++) {
                int base = (warp_n * 64 + ni * 8 + g) * RS + ko + l;
                bf[ni][0] = Bu[base];
                bf[ni][1] = Bu[base + 4];
            }
            #pragma unroll
            for (int mi = 0; mi < 2; mi++)
                #pragma unroll
                for (int ni = 0; ni < 8; ni++)
                    mma16(acc[mi][ni], af[mi], bf[ni]);
        }
        __syncthreads();
    }

    // epilogue
    #pragma unroll
    for (int mi = 0; mi < 2; mi++) {
        int r0 = mBase + warp_m * 32 + mi * 16 + g;
        int r1 = r0 + 8;
        #pragma unroll
        for (int ni = 0; ni < 8; ni++) {
            int col = nBase + warp_n * 64 + ni * 8 + (l << 1);
            if (MODE == 0) {
                if (r0 < M)
                    *reinterpret_cast<__half2*>(g_h1f + (size_t)r0 * HID_D + col) =
                        __floats2half2_rn(acc[mi][ni][0], acc[mi][ni][1]);
                if (r1 < M)
                    *reinterpret_cast<__half2*>(g_h1f + (size_t)r1 * HID_D + col) =
                        __floats2half2_rn(acc[mi][ni][2], acc[mi][ni][3]);
            } else {
                float2 bb = *reinterpret_cast<const float2*>(bias + col);
                float* C = out;
                if (r0 < M) {
                    float2 o; o.x = acc[mi][ni][0] + bb.x; o.y = acc[mi][ni][1] + bb.y;
                    *reinterpret_cast<float2*>(C + (size_t)r0 * LAT_D + col) = o;
                }
                if (r1 < M) {
                    float2 o; o.x = acc[mi][ni][2] + bb.x; o.y = acc[mi][ni][3] + bb.y;
                    *reinterpret_cast<float2*>(C + (size_t)r1 * LAT_D + col) = o;
                }
            }
        }
    }
}

// ---------------- fat: gemm1 + CSR fill ----------------
__global__ __launch_bounds__(256) void k_gemm1_fill(
    const int* __restrict__ ei, const float* __restrict__ ea)
{
    if (blockIdx.x < G1BLK) {
        gemm_body<0>(blockIdx.x & 1, blockIdx.x >> 1, nullptr, nullptr);
    } else {
        int e = (blockIdx.x - G1BLK) * 256 + threadIdx.x;
        if (e < EE) {
            int s = ei[e];
            int d = ei[EE + e];
            int pos = atomicAdd(&g_cnt[d], 1);
            g_srcs[pos] = s;
            g_nrm2[pos] = g_dis[s] * ea[e] * g_dis[d];
        }
    }
}

// ---------------- fat: gemm2 (mu/logvar) + scratch reset ----------------
__global__ __launch_bounds__(256) void k_gemm2_reset(
    const float* __restrict__ bmu, const float* __restrict__ blv,
    float* __restrict__ out)
{
    if (blockIdx.x < G2BLK) {
        int bx = blockIdx.x & 1;
        gemm_body<1>(bx, blockIdx.x >> 1, bx ? blv : bmu,
                     out + (size_t)bx * NN * LAT_D);
    } else {
        int i = (blockIdx.x - G2BLK) * 256 + threadIdx.x;
        if (i < NN) { g_deg[i] = 0.0f; g_cnt[i] = 0; }
    }
}

// ---------------- gather aggregation (fp16 features, fp32 accumulate) ----------------
// 32 threads per node (8 channels each, 16B load); 8 nodes per block
// PHASE 0: feat = g_h1f;  out = g_hidf = relu(agg + b1)  (fp16)
// PHASE 1: feat = g_hidf; out = g_aggf (fp16)
template<int PHASE>
__global__ __launch_bounds__(256) void k_gather(const float* __restrict__ b1) {
    int node = (blockIdx.x << 3) + (threadIdx.x >> 5);
    if (node >= NN) return;
    int c = (threadIdx.x & 31) << 3;
    const __half* feat = (PHASE == 0) ? g_h1f : g_hidf;

    float ds = g_dis[node];
    float dsq = ds * ds;
    float acc[8], v[8];
    {
        uint4 u = *reinterpret_cast<const uint4*>(feat + (size_t)node * HID_D + c);
        unpack8(u, v);
        #pragma unroll
        for (int i = 0; i < 8; i++) acc[i] = dsq * v[i];
    }

    int beg = g_rowptr[node];
    int end = g_rowptr[node + 1];
    int j = beg;
    for (; j + 1 < end; j += 2) {
        int   s0 = __ldg(&g_srcs[j]);
        int   s1 = __ldg(&g_srcs[j + 1]);
        float n0 = __ldg(&g_nrm2[j]);
        float n1 = __ldg(&g_nrm2[j + 1]);
        uint4 u0 = *reinterpret_cast<const uint4*>(feat + (size_t)s0 * HID_D + c);
        uint4 u1 = *reinterpret_cast<const uint4*>(feat + (size_t)s1 * HID_D + c);
        float w0[8], w1[8];
        unpack8(u0, w0);
        unpack8(u1, w1);
        #pragma unroll
        for (int i = 0; i < 8; i++) acc[i] = fmaf(w0[i], n0, acc[i]);
        #pragma unroll
        for (int i = 0; i < 8; i++) acc[i] = fmaf(w1[i], n1, acc[i]);
    }
    if (j < end) {
        int   s0 = __ldg(&g_srcs[j]);
        float n0 = __ldg(&g_nrm2[j]);
        uint4 u0 = *reinterpret_cast<const uint4*>(feat + (size_t)s0 * HID_D + c);
        float w0[8];
        unpack8(u0, w0);
        #pragma unroll
        for (int i = 0; i < 8; i++) acc[i] = fmaf(w0[i], n0, acc[i]);
    }

    uint4 u;
    if (PHASE == 0) {
        float4 bb0 = *reinterpret_cast<const float4*>(b1 + c);
        float4 bb1 = *reinterpret_cast<const float4*>(b1 + c + 4);
        float h[8];
        h[0] = fmaxf(acc[0] + bb0.x, 0.0f); h[1] = fmaxf(acc[1] + bb0.y, 0.0f);
        h[2] = fmaxf(acc[2] + bb0.z, 0.0f); h[3] = fmaxf(acc[3] + bb0.w, 0.0f);
        h[4] = fmaxf(acc[4] + bb1.x, 0.0f); h[5] = fmaxf(acc[5] + bb1.y, 0.0f);
        h[6] = fmaxf(acc[6] + bb1.z, 0.0f); h[7] = fmaxf(acc[7] + bb1.w, 0.0f);
        *reinterpret_cast<__half2*>(&u.x) = __floats2half2_rn(h[0], h[1]);
        *reinterpret_cast<__half2*>(&u.y) = __floats2half2_rn(h[2], h[3]);
        *reinterpret_cast<__half2*>(&u.z) = __floats2half2_rn(h[4], h[5]);
        *reinterpret_cast<__half2*>(&u.w) = __floats2half2_rn(h[6], h[7]);
        *reinterpret_cast<uint4*>(g_hidf + (size_t)node * HID_D + c) = u;
    } else {
        *reinterpret_cast<__half2*>(&u.x) = __floats2half2_rn(acc[0], acc[1]);
        *reinterpret_cast<__half2*>(&u.y) = __floats2half2_rn(acc[2], acc[3]);
        *reinterpret_cast<__half2*>(&u.z) = __floats2half2_rn(acc[4], acc[5]);
        *reinterpret_cast<__half2*>(&u.w) = __floats2half2_rn(acc[6], acc[7]);
        *reinterpret_cast<uint4*>(g_aggf + (size_t)node * HID_D + c) = u;
    }
}

// ---------------- launch ----------------
extern "C" void kernel_launch(void* const* d_in, const int* in_sizes, int n_in,
                              void* d_out, int out_size) {
    const float* x   = (const float*)d_in[0];
    const int*   ei  = (const int*)d_in[1];     // [2, E] int32
    const float* ea  = (const float*)d_in[2];
    const float* W1  = (const float*)d_in[3];
    const float* b1  = (const float*)d_in[4];
    const float* Wmu = (const float*)d_in[5];
    const float* bmu = (const float*)d_in[6];
    const float* Wlv = (const float*)d_in[7];
    const float* blv = (const float*)d_in[8];
    float* out = (float*)d_out;

    const int TB = 256;
    int gE = (EE + TB - 1) / TB;   // 3125

    // ---- fat prep: x->fp16 | W->fp16 transposed | deg/cnt histogram ----
    k_prep<<<CVX + CVW + gE, TB>>>(x, W1, Wmu, Wlv, ei, ea);

    // ---- scans (+dis) ----
    k_scan1<<<SCB, 256>>>();
    k_scan2<<<1, 256>>>();
    k_scan3<<<SCB, 256>>>();

    // ---- fat: conv1 transform (fp16 HMMA) + CSR fill ----
    k_gemm1_fill<<<G1BLK + gE, 256>>>(ei, ea);

    // ---- aggregate conv1 (+bias+relu) / conv2 ----
    int gG = (NN + 7) / 8;
    k_gather<0><<<gG, 256>>>(b1);
    k_gather<1><<<gG, 256>>>(b1);

    // ---- fat: mu / logvar GEMMs + scratch reset ----
    k_gemm2_reset<<<G2BLK + SCB, 256>>>(bmu, blv, out);
}